// round 13
// baseline (speedup 1.0000x reference)
#include <cuda_runtime.h>
#include <cuda_bf16.h>
#include <cstdint>

// ---------------- problem constants ----------------
namespace {
constexpr int Bn = 32;
constexpr int S  = 512;
constexpr int H  = 768;
constexpr int NN = 32;
constexpr int T  = 32;
constexpr int NE = 256;
constexpr int AE = 128;
constexpr int RL = 8;
constexpr float SCALE = 0.0625f;
constexpr float NEG   = 0.01f;
}

// ---------------- scratch ----------------
__device__ float g_probs[Bn * S * S];
__device__ float g_msg1 [Bn * NN * RL * H];
__device__ float g_msg2 [Bn * NN * RL * H];
__device__ float g_qe   [2 * Bn * RL * NE];
__device__ float g_qeP  [6 * 512 * NE];         // split-K partial slabs
__device__ float g_z    [2 * Bn * RL * H];
__device__ float g_zP   [2 * 512 * H];
__device__ float g_c    [2 * Bn * RL];
__device__ float g_att1 [Bn * NN];
__device__ float g_att2 [Bn * NN];
__device__ float g_u    [2 * H + 1];
__device__ float g_md   [2 * Bn * NN];
__device__ float g_feas [2 * Bn];
__device__ float g_bias [1280];

__device__ __nv_bfloat16 g_Wh  [1280 * H], g_Wl  [1280 * H];  // stacked WqT|WkT|WvT
__device__ __nv_bfloat16 g_WkNh[H * NE],   g_WkNl[H * NE];    // Wk original layout
__device__ __nv_bfloat16 g_qeh [512 * NE], g_qel [512 * NE];
__device__ __nv_bfloat16 g_xh  [Bn * S * H], g_xl [Bn * S * H];
__device__ __nv_bfloat16 g_qkh [Bn * S * 512], g_qkl[Bn * S * 512];
__device__ __nv_bfloat16 g_vTh [Bn * H * S], g_vTl[Bn * H * S];
__device__ __nv_bfloat16 g_ph  [Bn * S * S], g_pl [Bn * S * S];
__device__ __nv_bfloat16 g_qAh [512 * H],   g_qAl [512 * H];

// ---------------- helpers ----------------
__device__ __forceinline__ uint32_t smem_u32(const void* p) {
    uint32_t a;
    asm("{ .reg .u64 t; cvta.to.shared.u64 t, %1; cvt.u32.u64 %0, t; }" : "=r"(a) : "l"(p));
    return a;
}
__device__ __forceinline__ uint32_t bpack(__nv_bfloat16 a, __nv_bfloat16 b) {
    __nv_bfloat162 t = __halves2bfloat162(a, b);
    return *reinterpret_cast<uint32_t*>(&t);
}
__device__ __forceinline__ uint32_t fpack(float a, float b) {
    __nv_bfloat162 t = __floats2bfloat162_rn(a, b);
    return *reinterpret_cast<uint32_t*>(&t);
}
__device__ __forceinline__ void split4(float4 v, uint2& hv, uint2& lv) {
    __nv_bfloat16 h0 = __float2bfloat16(v.x), h1 = __float2bfloat16(v.y);
    __nv_bfloat16 h2 = __float2bfloat16(v.z), h3 = __float2bfloat16(v.w);
    hv.x = bpack(h0, h1); hv.y = bpack(h2, h3);
    lv.x = fpack(v.x - __bfloat162float(h0), v.y - __bfloat162float(h1));
    lv.y = fpack(v.z - __bfloat162float(h2), v.w - __bfloat162float(h3));
}
__device__ __forceinline__ void ldsm4(uint32_t& r0, uint32_t& r1, uint32_t& r2,
                                      uint32_t& r3, uint32_t a) {
    asm volatile("ldmatrix.sync.aligned.m8n8.x4.shared.b16 {%0,%1,%2,%3}, [%4];"
                 : "=r"(r0), "=r"(r1), "=r"(r2), "=r"(r3) : "r"(a));
}
__device__ __forceinline__ void mma16816(float* d, const uint32_t* a, const uint32_t* b) {
    asm volatile(
        "mma.sync.aligned.m16n8k16.row.col.f32.bf16.bf16.f32 "
        "{%0,%1,%2,%3}, {%4,%5,%6,%7}, {%8,%9}, {%0,%1,%2,%3};"
        : "+f"(d[0]), "+f"(d[1]), "+f"(d[2]), "+f"(d[3])
        : "r"(a[0]), "r"(a[1]), "r"(a[2]), "r"(a[3]), "r"(b[0]), "r"(b[1]));
}

// ================= all-bf16 cp.async bf16x3 GEMM, CTA 128x128 =================
// 8 warps (2x4), warp tile 64x32, BK=64, 3-stage pipeline, ONE sync per chunk.
// issue(c+2) targets buf (c+2)%3, disjoint from compute buf c%3 and in-flight
// (c+1)%3; the single sync orders compute(c-1)'s reads of (c+2)%3 before reuse.
// ROWB=144: row stride 9 octets (odd) -> ldmatrix conflict-free.
// EPI 0: fp32 out.  EPI 3: qkv routing (qk pairs / v SMEM-transposed pairs).
// SK: blockIdx.z = K-slice (length K); output slab at Cf + bz*sC.
constexpr int ROWB  = 144;
constexpr int MTILE = 128 * ROWB;     // 18432
constexpr int STG   = 4 * MTILE;      // 73728
constexpr int BG_SMEM = 3 * STG;      // 221184

template<int EPI, bool SK>
__global__ __launch_bounds__(256, 1) void bgemm(
    const __nv_bfloat16* __restrict__ Ahp, const __nv_bfloat16* __restrict__ Alp,
    const __nv_bfloat16* __restrict__ Bhp, const __nv_bfloat16* __restrict__ Blp,
    const float* __restrict__ bias, float* __restrict__ Cf,
    __nv_bfloat16* __restrict__ Ch, __nv_bfloat16* __restrict__ Cl,
    __nv_bfloat16* __restrict__ Dh, __nv_bfloat16* __restrict__ Dl,
    int lda, int ldb, int ldc, int K, float alpha,
    long long sA, long long sB, long long sC)
{
    extern __shared__ char smem[];
    const uint32_t sb = smem_u32(smem);
    const int tid = threadIdx.x, w = tid >> 5, lane = tid & 31;
    const int m0 = blockIdx.y * 128, n0 = blockIdx.x * 128, bz = blockIdx.z;
    int koff = 0;
    if (SK) {
        koff = bz * K;
        Cf += bz * sC;
    } else {
        Ahp += bz * sA; Alp += bz * sA;
        Bhp += bz * sB; Blp += bz * sB;
        if (EPI == 0) Cf += bz * sC;
    }

    const int wm = (w >> 2) * 64, wn = (w & 3) * 32;
    float acc[4][4][4];
#pragma unroll
    for (int a = 0; a < 4; a++)
#pragma unroll
        for (int b = 0; b < 4; b++)
#pragma unroll
            for (int c = 0; c < 4; c++) acc[a][b][c] = 0.f;

    const int nch = K >> 6;   // BK = 64

    auto issue = [&](int c) {
        if (c < nch) {
            const int k0 = (c << 6) + koff;
            const uint32_t dstb = sb + (c % 3) * STG;
#pragma unroll
            for (int mat = 0; mat < 4; mat++) {
                const __nv_bfloat16* g = (mat == 0) ? Ahp : (mat == 1) ? Alp
                                       : (mat == 2) ? Bhp : Blp;
                const int rb = (mat < 2) ? m0 : n0;
                const int ld = (mat < 2) ? lda : ldb;
#pragma unroll
                for (int it = 0; it < 4; ++it) {
                    int i = (it << 8) + tid, row = i >> 3, c8 = i & 7;
                    const __nv_bfloat16* src = g + (long long)(rb + row) * ld + k0 + (c8 << 3);
                    asm volatile("cp.async.cg.shared.global [%0], [%1], 16;"
                                 :: "r"(dstb + mat * MTILE + row * ROWB + (c8 << 4)), "l"(src));
                }
            }
        }
        asm volatile("cp.async.commit_group;");
    };

    const int q = lane >> 3, r = lane & 7;
    const int aRow = ((q & 1) << 3) + r;
    const int aCol = (q >> 1) << 4;
    const int bRow = ((q >> 1) << 3) + r;
    const int bCol = (q & 1) << 4;

    auto compute = [&](int c) {
        const uint32_t Ah = sb + (c % 3) * STG;
        const uint32_t Al = Ah + MTILE, Bh = Ah + 2 * MTILE, Bl = Ah + 3 * MTILE;
#pragma unroll
        for (int s = 0; s < 4; s++) {
            const int kOff = s * 32;
            uint32_t ah[4][4], al[4][4];
#pragma unroll
            for (int mt = 0; mt < 4; mt++) {
                uint32_t off = (uint32_t)(wm + mt * 16 + aRow) * ROWB + kOff + aCol;
                ldsm4(ah[mt][0], ah[mt][1], ah[mt][2], ah[mt][3], Ah + off);
                ldsm4(al[mt][0], al[mt][1], al[mt][2], al[mt][3], Al + off);
            }
            uint32_t bh[4][2], bl[4][2];
#pragma unroll
            for (int np = 0; np < 2; np++) {
                uint32_t off = (uint32_t)(wn + np * 16 + bRow) * ROWB + kOff + bCol;
                ldsm4(bh[2 * np][0], bh[2 * np][1],
                      bh[2 * np + 1][0], bh[2 * np + 1][1], Bh + off);
                ldsm4(bl[2 * np][0], bl[2 * np][1],
                      bl[2 * np + 1][0], bl[2 * np + 1][1], Bl + off);
            }
#pragma unroll
            for (int mt = 0; mt < 4; mt++)
#pragma unroll
                for (int nt = 0; nt < 4; nt++) {
                    mma16816(acc[mt][nt], ah[mt], bh[nt]);
                    mma16816(acc[mt][nt], ah[mt], bl[nt]);
                    mma16816(acc[mt][nt], al[mt], bh[nt]);
                }
        }
    };

    issue(0); issue(1);
    for (int c = 0; c < nch; c++) {
        asm volatile("cp.async.wait_group 1;");
        __syncthreads();
        issue(c + 2);
        compute(c);
    }

    const int gid = lane >> 2, tig = lane & 3;

    if (EPI == 3 && n0 >= 512) {
        // v tile: transpose through SMEM (pipeline buffers are dead), then
        // write coalesced bf16 hi/lo pairs to the [b, nv, t] layout.
        float* st = (float*)smem;   // [n][m], stride 132 (conflict-free octets)
        __syncthreads();
#pragma unroll
        for (int mt = 0; mt < 4; mt++)
#pragma unroll
            for (int half = 0; half < 2; half++) {
                const int m = wm + mt * 16 + gid + half * 8;
#pragma unroll
                for (int nt = 0; nt < 4; nt++) {
                    const int n = wn + nt * 8 + tig * 2;
                    st[n * 132 + m]       = acc[mt][nt][half * 2 + 0] + bias[n0 + n];
                    st[(n + 1) * 132 + m] = acc[mt][nt][half * 2 + 1] + bias[n0 + n + 1];
                }
            }
        __syncthreads();
        const long long bb2 = m0 >> 9;
        const int t0 = m0 & 511, nvb = n0 - 512;
#pragma unroll
        for (int it = 0; it < 32; it++) {
            int i = it * 256 + tid;                 // 128 n-rows x 64 uint32
            int n = i >> 6, mc = (i & 63) << 1;
            float v0 = st[n * 132 + mc], v1 = st[n * 132 + mc + 1];
            __nv_bfloat16 h0 = __float2bfloat16(v0), h1 = __float2bfloat16(v1);
            long long gi = (bb2 * 768 + nvb + n) * 512 + t0 + mc;
            *(uint32_t*)&Dh[gi] = bpack(h0, h1);
            *(uint32_t*)&Dl[gi] =
                fpack(v0 - __bfloat162float(h0), v1 - __bfloat162float(h1));
        }
    } else {
#pragma unroll
        for (int mt = 0; mt < 4; mt++)
#pragma unroll
            for (int half = 0; half < 2; half++) {
                const long long m = m0 + wm + mt * 16 + gid + half * 8;
#pragma unroll
                for (int nt = 0; nt < 4; nt++) {
                    float v0 = acc[mt][nt][half * 2 + 0];
                    float v1 = acc[mt][nt][half * 2 + 1];
                    const int n = n0 + wn + nt * 8 + tig * 2;
                    if (EPI == 0) {
                        v0 *= alpha; v1 *= alpha;
                        if (bias) { v0 += bias[n]; v1 += bias[n + 1]; }
                        *(float2*)&Cf[m * ldc + n] = make_float2(v0, v1);
                    } else {  // EPI == 3, qk half
                        v0 += bias[n]; v1 += bias[n + 1];
                        __nv_bfloat16 h0 = __float2bfloat16(v0), h1 = __float2bfloat16(v1);
                        *(uint32_t*)&Ch[m * 512 + n] = bpack(h0, h1);
                        *(uint32_t*)&Cl[m * 512 + n] =
                            fpack(v0 - __bfloat162float(h0), v1 - __bfloat162float(h1));
                    }
                }
            }
    }
}

// ---------------- split-K finish: qe = sum(slabs) + bq; emit fp32 + pairs ----
__global__ void qe_finish()
{
    int idx = blockIdx.x * 256 + threadIdx.x;   // 32768 float4s
    int n4 = (idx % (NE / 4)) * 4;
    float4 s = ((const float4*)g_qeP)[idx];
#pragma unroll
    for (int k = 1; k < 6; k++) {
        float4 p = ((const float4*)g_qeP)[k * (512 * NE / 4) + idx];
        s.x += p.x; s.y += p.y; s.z += p.z; s.w += p.w;
    }
    s.x += g_bias[n4]; s.y += g_bias[n4 + 1];
    s.z += g_bias[n4 + 2]; s.w += g_bias[n4 + 3];
    ((float4*)g_qe)[idx] = s;
    uint2 hv, lv; split4(s, hv, lv);
    ((uint2*)g_qeh)[idx] = hv;
    ((uint2*)g_qel)[idx] = lv;
}

// ---------------- split-K finish: z = slab0 + slab1 --------------------------
__global__ void z_finish()
{
    int idx = blockIdx.x * 256 + threadIdx.x;   // 98304 float4s
    float4 a = ((const float4*)g_zP)[idx];
    float4 b = ((const float4*)g_zP)[512 * H / 4 + idx];
    a.x += b.x; a.y += b.y; a.z += b.z; a.w += b.w;
    ((float4*)g_z)[idx] = a;
}

// ---------------- weights: stacked WT pairs + WkN pairs + bias ---------------
// Reads are coalesced (consecutive tid -> consecutive W address); the
// transpose scatter is on the store side (stall-free).
__global__ void tsplit_all(const float* __restrict__ Wq, const float* __restrict__ Wk,
                           const float* __restrict__ Wv, const float* __restrict__ bq,
                           const float* __restrict__ bk, const float* __restrict__ bv)
{
    int idx = blockIdx.x * 256 + threadIdx.x;
    if (idx < 1280 * H) {
        // enumerate (k, n) with n fastest over the three stacked blocks
        const float* W; int Nn, nbase, local;
        if (idx < NE * H)            { W = Wq; Nn = NE; nbase = 0;   local = idx; }
        else if (idx < 2 * NE * H)   { W = Wk; Nn = NE; nbase = 256; local = idx - NE * H; }
        else                         { W = Wv; Nn = H;  nbase = 512; local = idx - 2 * NE * H; }
        int k = local / Nn, n = local - k * Nn;
        float x = W[local];                       // coalesced read
        __nv_bfloat16 h = __float2bfloat16(x);
        int oi = (nbase + n) * H + k;             // transposed scatter store
        g_Wh[oi] = h;
        g_Wl[oi] = __float2bfloat16(x - __bfloat162float(h));
    } else if (idx < 1280 * H + H * NE) {
        int local = idx - 1280 * H;
        float x = Wk[local];
        __nv_bfloat16 h = __float2bfloat16(x);
        g_WkNh[local] = h;
        g_WkNl[local] = __float2bfloat16(x - __bfloat162float(h));
    } else if (idx < 1280 * H + H * NE + 1280) {
        int j = idx - 1280 * H - H * NE;
        g_bias[j] = (j < 256) ? bq[j] : (j < 512) ? bk[j - 256] : bv[j - 512];
    }
}

// ---------------- gather + split region rows for qe GEMM ---------------------
__global__ void sgat_kernel(const float* __restrict__ xs)
{
    int idx = blockIdx.x * 256 + threadIdx.x;
    int m = idx / (H / 4), r4 = idx - m * (H / 4);
    int br = m >> 8, b = (m >> 3) & 31, l = m & 7;
    float4 v = ((const float4*)(xs + ((long long)b * S + (br ? 20 : 1) + l) * H))[r4];
    uint2 hv, lv; split4(v, hv, lv);
    ((uint2*)g_qAh)[idx] = hv;
    ((uint2*)g_qAl)[idx] = lv;
}

// ---------------- c[row] = qe[row]·bk ----------------------------------------
__global__ void c_kernel()
{
    int row = blockIdx.x * 8 + (threadIdx.x >> 5);
    int lane = threadIdx.x & 31;
    float p = 0.f;
#pragma unroll
    for (int i = 0; i < 8; i++) {
        int e = lane + i * 32;
        p += g_qe[row * NE + e] * g_bias[256 + e];
    }
#pragma unroll
    for (int o = 16; o > 0; o >>= 1) p += __shfl_xor_sync(0xffffffffu, p, o);
    if (lane == 0) g_c[row] = p;
}

// ---------------- u = Wa @ Wattn halves; cbase -------------------------------
__global__ void u_kernel(const float* __restrict__ Wa, const float* __restrict__ Wattn,
                         const float* __restrict__ ba, const float* __restrict__ battn)
{
    if (blockIdx.x < 48) {
        int gt = blockIdx.x * 256 + threadIdx.x;
        int g = gt >> 3, sub = gt & 7;
        int j = g / H, h = g - j * H;
        float acc = 0.f;
#pragma unroll 4
        for (int a = sub; a < AE; a += 8) acc += Wa[h * AE + a] * Wattn[j * AE + a];
        acc += __shfl_down_sync(0xffffffffu, acc, 4, 8);
        acc += __shfl_down_sync(0xffffffffu, acc, 2, 8);
        acc += __shfl_down_sync(0xffffffffu, acc, 1, 8);
        if (sub == 0) g_u[g] = acc;
    } else {
        __shared__ float red[256];
        int tid = threadIdx.x;
        float v = 0.f;
        if (tid < AE) v = ba[tid] * (Wattn[tid] + Wattn[AE + tid]);
        red[tid] = v; __syncthreads();
        for (int s2 = 128; s2 > 0; s2 >>= 1) {
            if (tid < s2) red[tid] += red[tid + s2];
            __syncthreads();
        }
        if (tid == 0) g_u[2 * H] = red[0] + battn[0];
    }
}

// ---------------- per-(br,b,n): scores from z -> softmax -> message ----------
// es rows stride 196 floats (16B-aligned, conflict-free LDS.128 across lanes)
__global__ __launch_bounds__(256) void neigh_kernel(
    const float* __restrict__ e1, const float* __restrict__ e2)
{
    __shared__ float zs[RL * H];        // 24 KB
    __shared__ float es[T * 196];       // 25 KB (chunk Hc=192, stride 196)
    __shared__ float aw[RL * T];
    __shared__ float cs[RL];
    int br = blockIdx.x >> 10;
    int b = (blockIdx.x >> 5) & 31, n = blockIdx.x & 31;
    int tid = threadIdx.x;
    const float* emb = (br ? e2 : e1) + (long long)(b * NN + n) * T * H;
    const float4* eb4 = (const float4*)emb;

    const float4* z4 = (const float4*)(g_z + (long long)(br * 256 + b * 8) * H);
#pragma unroll
    for (int it = 0; it < 6; it++) {
        int i = it * 256 + tid;
        *(float4*)&zs[i * 4] = z4[i];
    }
    if (tid < 8) cs[tid] = g_c[br * 256 + b * 8 + tid];
    __syncthreads();

    int l = tid >> 5, tt = tid & 31;
    float sacc = 0.f;
#pragma unroll
    for (int ch = 0; ch < 4; ch++) {
        for (int i = tid; i < T * 48; i += 256) {
            int t2 = i / 48, h4 = i - t2 * 48;
            *(float4*)&es[t2 * 196 + h4 * 4] = eb4[t2 * (H / 4) + ch * 48 + h4];
        }
        __syncthreads();
        const float4* er = (const float4*)&es[tt * 196];
        const float4* zr = (const float4*)&zs[l * H + ch * 192];
#pragma unroll 8
        for (int j = 0; j < 48; j++) {
            float4 e = er[j], zv = zr[j];
            sacc += e.x * zv.x + e.y * zv.y + e.z * zv.z + e.w * zv.w;
        }
        __syncthreads();
    }
    float s = (sacc + cs[l]) * SCALE;
    float m = s;
#pragma unroll
    for (int o = 16; o > 0; o >>= 1) m = fmaxf(m, __shfl_xor_sync(0xffffffffu, m, o));
    float ex = __expf(s - m), sum = ex;
#pragma unroll
    for (int o = 16; o > 0; o >>= 1) sum += __shfl_xor_sync(0xffffffffu, sum, o);
    aw[l * T + tt] = ex / sum;
    __syncthreads();

    float* msg = (br ? g_msg2 : g_msg1) + (long long)(b * NN + n) * RL * H;
    float4* mb4 = (float4*)msg;
#pragma unroll
    for (int it = 0; it < RL * H / 4 / 256; it++) {
        int idx = it * 256 + tid;
        int l2 = idx / (H / 4), h4 = idx - l2 * (H / 4);
        float4 acc = make_float4(0.f, 0.f, 0.f, 0.f);
        const float* awr = aw + l2 * T;
#pragma unroll 8
        for (int t2 = 0; t2 < T; t2++) {
            float wgt = awr[t2];
            float4 e = eb4[t2 * (H / 4) + h4];
            acc.x += wgt * e.x; acc.y += wgt * e.y;
            acc.z += wgt * e.z; acc.w += wgt * e.w;
        }
        mb4[idx] = acc;
    }
}

// ---------------- region gate dots -------------------------------------------
__global__ __launch_bounds__(128) void rscore_kernel(
    const float* __restrict__ xs, const float* __restrict__ msg1,
    const float* __restrict__ msg2)
{
    __shared__ float wred[4];
    int id = blockIdx.x;
    int br = id / (Bn * 33);
    int rem = id - br * (Bn * 33);
    int b = rem / 33, j = rem - b * 33;
    int tid = threadIdx.x;

    const float* src;
    const float* uvec;
    if (j < NN) {
        src = (br ? msg2 : msg1) + (long long)(b * NN + j) * RL * H;
        uvec = g_u + H;
    } else {
        src = xs + ((long long)b * S + (br ? 20 : 1)) * H;
        uvec = g_u;
    }
    const float4* s4 = (const float4*)src;
    float p = 0.f;
#pragma unroll
    for (int it = 0; it < RL * H / 4 / 128; it++) {
        int i = it * 128 + tid;
        float4 v = s4[i];
        const float* up = uvec + (i % (H / 4)) * 4;
        p += v.x * up[0] + v.y * up[1] + v.z * up[2] + v.w * up[3];
    }
#pragma unroll
    for (int o = 16; o > 0; o >>= 1) p += __shfl_xor_sync(0xffffffffu, p, o);
    if ((tid & 31) == 0) wred[tid >> 5] = p;
    __syncthreads();
    if (tid == 0) {
        float tot = (wred[0] + wred[1] + wred[2] + wred[3]) * (1.f / RL);
        if (j < NN) g_md[(br * Bn + b) * NN + j] = tot;
        else        g_feas[br * Bn + b] = tot;
    }
}

__global__ void rsoftmax_kernel(const float* __restrict__ dist1,
                                const float* __restrict__ dist2,
                                const float* __restrict__ wb,
                                const float* __restrict__ bb)
{
    int br = blockIdx.x >> 5, b = blockIdx.x & 31;
    int lane = threadIdx.x;
    float pre = g_feas[br * Bn + b] + g_md[(br * Bn + b) * NN + lane] + g_u[2 * H];
    float z = pre >= 0.f ? pre : NEG * pre;
    const float* dist = br ? dist2 : dist1;
    float v = z + dist[b * NN + lane] * wb[0] + bb[0];
    float m = v;
#pragma unroll
    for (int o = 16; o > 0; o >>= 1) m = fmaxf(m, __shfl_xor_sync(0xffffffffu, m, o));
    float e = __expf(v - m), s = e;
#pragma unroll
    for (int o = 16; o > 0; o >>= 1) s += __shfl_xor_sync(0xffffffffu, s, o);
    (br ? g_att2 : g_att1)[b * NN + lane] = e / s;
}

// ---------------- x = xs (+ gated messages) -> bf16 pairs --------------------
__global__ void build_x_kernel(const float* __restrict__ xs)
{
    int idx = blockIdx.x * 256 + threadIdx.x;
    float4 v = ((const float4*)xs)[idx];
    int h4 = idx % (H / 4);
    int s = (idx / (H / 4)) % S;
    int b = idx / (S * H / 4);
    if (s >= 1 && s < 9) {
        int l = s - 1;
        const float4* m4 = (const float4*)g_msg1;
#pragma unroll 4
        for (int n = 0; n < NN; n++) {
            float a = g_att1[b * NN + n];
            float4 m = m4[((b * NN + n) * RL + l) * (H / 4) + h4];
            v.x += a * m.x; v.y += a * m.y; v.z += a * m.z; v.w += a * m.w;
        }
    } else if (s >= 20 && s < 28) {
        int l = s - 20;
        const float4* m4 = (const float4*)g_msg2;
#pragma unroll 4
        for (int n = 0; n < NN; n++) {
            float a = g_att2[b * NN + n];
            float4 m = m4[((b * NN + n) * RL + l) * (H / 4) + h4];
            v.x += a * m.x; v.y += a * m.y; v.z += a * m.z; v.w += a * m.w;
        }
    }
    uint2 hv, lv; split4(v, hv, lv);
    ((uint2*)g_xh)[idx] = hv;
    ((uint2*)g_xl)[idx] = lv;
}

// ---------------- row softmax (warp/row) -> bf16 pairs -----------------------
__global__ __launch_bounds__(256) void softmax_rows_kernel()
{
    int warp = threadIdx.x >> 5, lane = threadIdx.x & 31;
    long long row = (long long)blockIdx.x * 8 + warp;
    const float4* r4 = (const float4*)(g_probs + row * S);
    float4 x[4];
    float m = -3.4e38f;
#pragma unroll
    for (int k = 0; k < 4; k++) {
        x[k] = r4[lane + 32 * k];
        m = fmaxf(m, fmaxf(fmaxf(x[k].x, x[k].y), fmaxf(x[k].z, x[k].w)));
    }
#pragma unroll
    for (int o = 16; o > 0; o >>= 1) m = fmaxf(m, __shfl_xor_sync(0xffffffffu, m, o));
    float s = 0.f;
#pragma unroll
    for (int k = 0; k < 4; k++) {
        x[k].x = __expf(x[k].x - m); x[k].y = __expf(x[k].y - m);
        x[k].z = __expf(x[k].z - m); x[k].w = __expf(x[k].w - m);
        s += x[k].x + x[k].y + x[k].z + x[k].w;
    }
#pragma unroll
    for (int o = 16; o > 0; o >>= 1) s += __shfl_xor_sync(0xffffffffu, s, o);
    float inv = 1.f / s;
    uint2* ph4 = (uint2*)(g_ph + row * S);
    uint2* pl4 = (uint2*)(g_pl + row * S);
#pragma unroll
    for (int k = 0; k < 4; k++) {
        x[k].x *= inv; x[k].y *= inv; x[k].z *= inv; x[k].w *= inv;
        uint2 hv, lv; split4(x[k], hv, lv);
        ph4[lane + 32 * k] = hv;
        pl4[lane + 32 * k] = lv;
    }
}

// ---------------- launch ----------------
extern "C" void kernel_launch(void* const* d_in, const int* in_sizes, int n_in,
                              void* d_out, int out_size)
{
    const float* xs    = (const float*)d_in[0];
    const float* n1emb = (const float*)d_in[1];
    const float* n2emb = (const float*)d_in[2];
    const float* dist1 = (const float*)d_in[3];
    const float* dist2 = (const float*)d_in[4];
    const float* Wq    = (const float*)d_in[5];
    const float* bq    = (const float*)d_in[6];
    const float* Wk    = (const float*)d_in[7];
    const float* bk    = (const float*)d_in[8];
    const float* Wv    = (const float*)d_in[9];
    const float* bv    = (const float*)d_in[10];
    const float* Wa    = (const float*)d_in[11];
    const float* ba    = (const float*)d_in[12];
    const float* Wattn = (const float*)d_in[13];
    const float* battn = (const float*)d_in[14];
    const float* wb    = (const float*)d_in[15];
    const float* bb    = (const float*)d_in[16];
    float* out = (float*)d_out;

    float *pp, *pm1, *pm2, *pqeP, *pzP, *pbias;
    __nv_bfloat16 *pwh, *pwl, *pwknh, *pwknl, *pqeh, *pqel, *pxh, *pxl,
                  *pqkh, *pqkl, *pvh, *pvl, *pph, *ppl, *pah, *pal;
    cudaGetSymbolAddress((void**)&pp,    g_probs);
    cudaGetSymbolAddress((void**)&pm1,   g_msg1);
    cudaGetSymbolAddress((void**)&pm2,   g_msg2);
    cudaGetSymbolAddress((void**)&pqeP,  g_qeP);
    cudaGetSymbolAddress((void**)&pzP,   g_zP);
    cudaGetSymbolAddress((void**)&pbias, g_bias);
    cudaGetSymbolAddress((void**)&pwh,   g_Wh);
    cudaGetSymbolAddress((void**)&pwl,   g_Wl);
    cudaGetSymbolAddress((void**)&pwknh, g_WkNh);
    cudaGetSymbolAddress((void**)&pwknl, g_WkNl);
    cudaGetSymbolAddress((void**)&pqeh,  g_qeh);
    cudaGetSymbolAddress((void**)&pqel,  g_qel);
    cudaGetSymbolAddress((void**)&pxh,   g_xh);
    cudaGetSymbolAddress((void**)&pxl,   g_xl);
    cudaGetSymbolAddress((void**)&pqkh,  g_qkh);
    cudaGetSymbolAddress((void**)&pqkl,  g_qkl);
    cudaGetSymbolAddress((void**)&pvh,   g_vTh);
    cudaGetSymbolAddress((void**)&pvl,   g_vTl);
    cudaGetSymbolAddress((void**)&pph,   g_ph);
    cudaGetSymbolAddress((void**)&ppl,   g_pl);
    cudaGetSymbolAddress((void**)&pah,   g_qAh);
    cudaGetSymbolAddress((void**)&pal,   g_qAl);

    cudaFuncSetAttribute(bgemm<0, false>, cudaFuncAttributeMaxDynamicSharedMemorySize, BG_SMEM);
    cudaFuncSetAttribute(bgemm<0, true>,  cudaFuncAttributeMaxDynamicSharedMemorySize, BG_SMEM);
    cudaFuncSetAttribute(bgemm<3, false>, cudaFuncAttributeMaxDynamicSharedMemorySize, BG_SMEM);

    // prep
    tsplit_all<<<(1280 * H + H * NE + 1280 + 255) / 256, 256>>>(Wq, Wk, Wv, bq, bk, bv);
    u_kernel<<<49, 256>>>(Wa, Wattn, ba, battn);
    sgat_kernel<<<512 * (H / 4) / 256, 256>>>(xs);

    // qe slabs: split-K 6 x 128 over K=768  (grid 2x4x6 = 48 CTAs)
    bgemm<0, true><<<dim3(2, 4, 6), 256, BG_SMEM>>>(
        pah, pal, pwh, pwl, nullptr, pqeP, nullptr, nullptr, nullptr, nullptr,
        H, H, NE, 128, 1.f, 0, 0, (long long)512 * NE);
    qe_finish<<<128, 256>>>();

    // z slabs: split-K 2 x 128 over K=256 (grid 6x4x2 = 48 CTAs)
    bgemm<0, true><<<dim3(6, 4, 2), 256, BG_SMEM>>>(
        pqeh, pqel, pwknh, pwknl, nullptr, pzP, nullptr, nullptr, nullptr, nullptr,
        NE, NE, H, 128, 1.f, 0, 0, (long long)512 * H);
    z_finish<<<384, 256>>>();
    c_kernel<<<64, 256>>>();

    // neighbor attention via emb·z + messages (both branches)
    neigh_kernel<<<2 * Bn * NN, 256>>>(n1emb, n2emb);

    // gate attention + x pairs
    rscore_kernel<<<2 * Bn * 33, 128>>>(xs, pm1, pm2);
    rsoftmax_kernel<<<2 * Bn, 32>>>(dist1, dist2, wb, bb);
    build_x_kernel<<<(Bn * S * H / 4) / 256, 256>>>(xs);

    // fused q/k/v projections: M = 16384 -> 128 M-tiles, N = 1280 -> 10 N-tiles
    bgemm<3, false><<<dim3(10, 128, 1), 256, BG_SMEM>>>(
        pxh, pxl, pwh, pwl, pbias, nullptr, pqkh, pqkl, pvh, pvl,
        H, H, 512, H, 1.f, 0, 0, 0);

    // scores = SCALE * q @ k^T (batched, grid 4x4x32 = 512)
    bgemm<0, false><<<dim3(4, 4, 32), 256, BG_SMEM>>>(
        pqkh, pqkl, pqkh + 256, pqkl + 256, nullptr, pp,
        nullptr, nullptr, nullptr, nullptr,
        512, 512, S, NE, SCALE,
        (long long)S * 512, (long long)S * 512, (long long)S * S);

    softmax_rows_kernel<<<Bn * S / 8, 256>>>();

    // out = probs @ v (batched, grid 6x4x32 = 768)
    bgemm<0, false><<<dim3(6, 4, 32), 256, BG_SMEM>>>(
        pph, ppl, pvh, pvl, nullptr, out, nullptr, nullptr, nullptr, nullptr,
        512, 512, H, S, 1.f,
        (long long)S * S, (long long)H * S, (long long)S * H);
}

// round 14
// speedup vs baseline: 1.0524x; 1.0524x over previous
#include <cuda_runtime.h>
#include <cuda_bf16.h>
#include <cstdint>

// ---------------- problem constants ----------------
namespace {
constexpr int Bn = 32;
constexpr int S  = 512;
constexpr int H  = 768;
constexpr int NN = 32;
constexpr int T  = 32;
constexpr int NE = 256;
constexpr int AE = 128;
constexpr int RL = 8;
constexpr float SCALE = 0.0625f;
constexpr float NEG   = 0.01f;
}

// ---------------- scratch ----------------
__device__ float g_probs[Bn * S * S];
__device__ float g_msg1 [Bn * NN * RL * H];
__device__ float g_msg2 [Bn * NN * RL * H];
__device__ float g_qe   [2 * Bn * RL * NE];
__device__ float g_qeP  [6 * 512 * NE];         // split-K partial slabs
__device__ float g_z    [2 * Bn * RL * H];
__device__ float g_zP   [2 * 512 * H];
__device__ float g_c    [2 * Bn * RL];
__device__ float g_att1 [Bn * NN];
__device__ float g_att2 [Bn * NN];
__device__ float g_u    [2 * H + 1];
__device__ float g_md   [2 * Bn * NN];
__device__ float g_feas [2 * Bn];
__device__ float g_bias [1280];

__device__ __nv_bfloat16 g_Wh  [1280 * H], g_Wl  [1280 * H];  // stacked WqT|WkT|WvT
__device__ __nv_bfloat16 g_WkNh[H * NE],   g_WkNl[H * NE];    // Wk original layout
__device__ __nv_bfloat16 g_qeh [512 * NE], g_qel [512 * NE];
__device__ __nv_bfloat16 g_xh  [Bn * S * H], g_xl [Bn * S * H];
__device__ __nv_bfloat16 g_qkh [Bn * S * 512], g_qkl[Bn * S * 512];
__device__ __nv_bfloat16 g_vTh [Bn * H * S], g_vTl[Bn * H * S];
__device__ __nv_bfloat16 g_ph  [Bn * S * S], g_pl [Bn * S * S];
__device__ __nv_bfloat16 g_qAh [512 * H],   g_qAl [512 * H];

// ---------------- helpers ----------------
__device__ __forceinline__ uint32_t smem_u32(const void* p) {
    uint32_t a;
    asm("{ .reg .u64 t; cvta.to.shared.u64 t, %1; cvt.u32.u64 %0, t; }" : "=r"(a) : "l"(p));
    return a;
}
__device__ __forceinline__ uint32_t bpack(__nv_bfloat16 a, __nv_bfloat16 b) {
    __nv_bfloat162 t = __halves2bfloat162(a, b);
    return *reinterpret_cast<uint32_t*>(&t);
}
__device__ __forceinline__ uint32_t fpack(float a, float b) {
    __nv_bfloat162 t = __floats2bfloat162_rn(a, b);
    return *reinterpret_cast<uint32_t*>(&t);
}
__device__ __forceinline__ void split4(float4 v, uint2& hv, uint2& lv) {
    __nv_bfloat16 h0 = __float2bfloat16(v.x), h1 = __float2bfloat16(v.y);
    __nv_bfloat16 h2 = __float2bfloat16(v.z), h3 = __float2bfloat16(v.w);
    hv.x = bpack(h0, h1); hv.y = bpack(h2, h3);
    lv.x = fpack(v.x - __bfloat162float(h0), v.y - __bfloat162float(h1));
    lv.y = fpack(v.z - __bfloat162float(h2), v.w - __bfloat162float(h3));
}
__device__ __forceinline__ void ldsm4(uint32_t& r0, uint32_t& r1, uint32_t& r2,
                                      uint32_t& r3, uint32_t a) {
    asm volatile("ldmatrix.sync.aligned.m8n8.x4.shared.b16 {%0,%1,%2,%3}, [%4];"
                 : "=r"(r0), "=r"(r1), "=r"(r2), "=r"(r3) : "r"(a));
}
__device__ __forceinline__ void mma16816(float* d, const uint32_t* a, const uint32_t* b) {
    asm volatile(
        "mma.sync.aligned.m16n8k16.row.col.f32.bf16.bf16.f32 "
        "{%0,%1,%2,%3}, {%4,%5,%6,%7}, {%8,%9}, {%0,%1,%2,%3};"
        : "+f"(d[0]), "+f"(d[1]), "+f"(d[2]), "+f"(d[3])
        : "r"(a[0]), "r"(a[1]), "r"(a[2]), "r"(a[3]), "r"(b[0]), "r"(b[1]));
}

// ================= all-bf16 cp.async bf16x3 GEMM, CTA 128x128 =================
// 8 warps (2x4), warp tile 64x32, BK=64, 3-stage pipeline, ONE sync per chunk.
// ROWB=144: row stride 9 octets (odd) -> ldmatrix conflict-free.
// EPI 0: fp32 out.  EPI 3: qkv routing (qk pairs / v SMEM-transposed pairs).
// SK: blockIdx.z = K-slice (length K); output slab at Cf + bz*sC.
constexpr int ROWB  = 144;
constexpr int MTILE = 128 * ROWB;     // 18432
constexpr int STG   = 4 * MTILE;      // 73728
constexpr int BG_SMEM = 3 * STG;      // 221184

template<int EPI, bool SK>
__global__ __launch_bounds__(256, 1) void bgemm(
    const __nv_bfloat16* __restrict__ Ahp, const __nv_bfloat16* __restrict__ Alp,
    const __nv_bfloat16* __restrict__ Bhp, const __nv_bfloat16* __restrict__ Blp,
    const float* __restrict__ bias, float* __restrict__ Cf,
    __nv_bfloat16* __restrict__ Ch, __nv_bfloat16* __restrict__ Cl,
    __nv_bfloat16* __restrict__ Dh, __nv_bfloat16* __restrict__ Dl,
    int lda, int ldb, int ldc, int K, float alpha,
    long long sA, long long sB, long long sC)
{
    extern __shared__ char smem[];
    const uint32_t sb = smem_u32(smem);
    const int tid = threadIdx.x, w = tid >> 5, lane = tid & 31;
    const int m0 = blockIdx.y * 128, n0 = blockIdx.x * 128, bz = blockIdx.z;
    int koff = 0;
    if (SK) {
        koff = bz * K;
        Cf += bz * sC;
    } else {
        Ahp += bz * sA; Alp += bz * sA;
        Bhp += bz * sB; Blp += bz * sB;
        if (EPI == 0) Cf += bz * sC;
    }

    const int wm = (w >> 2) * 64, wn = (w & 3) * 32;
    float acc[4][4][4];
#pragma unroll
    for (int a = 0; a < 4; a++)
#pragma unroll
        for (int b = 0; b < 4; b++)
#pragma unroll
            for (int c = 0; c < 4; c++) acc[a][b][c] = 0.f;

    const int nch = K >> 6;   // BK = 64

    auto issue = [&](int c) {
        if (c < nch) {
            const int k0 = (c << 6) + koff;
            const uint32_t dstb = sb + (c % 3) * STG;
#pragma unroll
            for (int mat = 0; mat < 4; mat++) {
                const __nv_bfloat16* g = (mat == 0) ? Ahp : (mat == 1) ? Alp
                                       : (mat == 2) ? Bhp : Blp;
                const int rb = (mat < 2) ? m0 : n0;
                const int ld = (mat < 2) ? lda : ldb;
#pragma unroll
                for (int it = 0; it < 4; ++it) {
                    int i = (it << 8) + tid, row = i >> 3, c8 = i & 7;
                    const __nv_bfloat16* src = g + (long long)(rb + row) * ld + k0 + (c8 << 3);
                    asm volatile("cp.async.cg.shared.global [%0], [%1], 16;"
                                 :: "r"(dstb + mat * MTILE + row * ROWB + (c8 << 4)), "l"(src));
                }
            }
        }
        asm volatile("cp.async.commit_group;");
    };

    const int q = lane >> 3, r = lane & 7;
    const int aRow = ((q & 1) << 3) + r;
    const int aCol = (q >> 1) << 4;
    const int bRow = ((q >> 1) << 3) + r;
    const int bCol = (q & 1) << 4;

    auto compute = [&](int c) {
        const uint32_t Ah = sb + (c % 3) * STG;
        const uint32_t Al = Ah + MTILE, Bh = Ah + 2 * MTILE, Bl = Ah + 3 * MTILE;
#pragma unroll
        for (int s = 0; s < 4; s++) {
            const int kOff = s * 32;
            uint32_t ah[4][4], al[4][4];
#pragma unroll
            for (int mt = 0; mt < 4; mt++) {
                uint32_t off = (uint32_t)(wm + mt * 16 + aRow) * ROWB + kOff + aCol;
                ldsm4(ah[mt][0], ah[mt][1], ah[mt][2], ah[mt][3], Ah + off);
                ldsm4(al[mt][0], al[mt][1], al[mt][2], al[mt][3], Al + off);
            }
            uint32_t bh[4][2], bl[4][2];
#pragma unroll
            for (int np = 0; np < 2; np++) {
                uint32_t off = (uint32_t)(wn + np * 16 + bRow) * ROWB + kOff + bCol;
                ldsm4(bh[2 * np][0], bh[2 * np][1],
                      bh[2 * np + 1][0], bh[2 * np + 1][1], Bh + off);
                ldsm4(bl[2 * np][0], bl[2 * np][1],
                      bl[2 * np + 1][0], bl[2 * np + 1][1], Bl + off);
            }
#pragma unroll
            for (int mt = 0; mt < 4; mt++)
#pragma unroll
                for (int nt = 0; nt < 4; nt++) {
                    mma16816(acc[mt][nt], ah[mt], bh[nt]);
                    mma16816(acc[mt][nt], ah[mt], bl[nt]);
                    mma16816(acc[mt][nt], al[mt], bh[nt]);
                }
        }
    };

    issue(0); issue(1);
    for (int c = 0; c < nch; c++) {
        asm volatile("cp.async.wait_group 1;");
        __syncthreads();
        issue(c + 2);
        compute(c);
    }

    const int gid = lane >> 2, tig = lane & 3;

    if (EPI == 3 && n0 >= 512) {
        // v tile: transpose through SMEM, then coalesced bf16 pair stores.
        float* st = (float*)smem;   // [n][m], stride 132
        __syncthreads();
#pragma unroll
        for (int mt = 0; mt < 4; mt++)
#pragma unroll
            for (int half = 0; half < 2; half++) {
                const int m = wm + mt * 16 + gid + half * 8;
#pragma unroll
                for (int nt = 0; nt < 4; nt++) {
                    const int n = wn + nt * 8 + tig * 2;
                    st[n * 132 + m]       = acc[mt][nt][half * 2 + 0] + bias[n0 + n];
                    st[(n + 1) * 132 + m] = acc[mt][nt][half * 2 + 1] + bias[n0 + n + 1];
                }
            }
        __syncthreads();
        const long long bb2 = m0 >> 9;
        const int t0 = m0 & 511, nvb = n0 - 512;
#pragma unroll
        for (int it = 0; it < 32; it++) {
            int i = it * 256 + tid;
            int n = i >> 6, mc = (i & 63) << 1;
            float v0 = st[n * 132 + mc], v1 = st[n * 132 + mc + 1];
            __nv_bfloat16 h0 = __float2bfloat16(v0), h1 = __float2bfloat16(v1);
            long long gi = (bb2 * 768 + nvb + n) * 512 + t0 + mc;
            *(uint32_t*)&Dh[gi] = bpack(h0, h1);
            *(uint32_t*)&Dl[gi] =
                fpack(v0 - __bfloat162float(h0), v1 - __bfloat162float(h1));
        }
    } else {
#pragma unroll
        for (int mt = 0; mt < 4; mt++)
#pragma unroll
            for (int half = 0; half < 2; half++) {
                const long long m = m0 + wm + mt * 16 + gid + half * 8;
#pragma unroll
                for (int nt = 0; nt < 4; nt++) {
                    float v0 = acc[mt][nt][half * 2 + 0];
                    float v1 = acc[mt][nt][half * 2 + 1];
                    const int n = n0 + wn + nt * 8 + tig * 2;
                    if (EPI == 0) {
                        v0 *= alpha; v1 *= alpha;
                        if (bias) { v0 += bias[n]; v1 += bias[n + 1]; }
                        *(float2*)&Cf[m * ldc + n] = make_float2(v0, v1);
                    } else {  // EPI == 3, qk half
                        v0 += bias[n]; v1 += bias[n + 1];
                        __nv_bfloat16 h0 = __float2bfloat16(v0), h1 = __float2bfloat16(v1);
                        *(uint32_t*)&Ch[m * 512 + n] = bpack(h0, h1);
                        *(uint32_t*)&Cl[m * 512 + n] =
                            fpack(v0 - __bfloat162float(h0), v1 - __bfloat162float(h1));
                    }
                }
            }
    }
}

// ---------------- split-K finish: qe = sum(slabs) + bq; emit fp32 + pairs ----
__global__ void qe_finish()
{
    int idx = blockIdx.x * 256 + threadIdx.x;   // 32768 float4s
    int n4 = (idx % (NE / 4)) * 4;
    float4 s = ((const float4*)g_qeP)[idx];
#pragma unroll
    for (int k = 1; k < 6; k++) {
        float4 p = ((const float4*)g_qeP)[k * (512 * NE / 4) + idx];
        s.x += p.x; s.y += p.y; s.z += p.z; s.w += p.w;
    }
    s.x += g_bias[n4]; s.y += g_bias[n4 + 1];
    s.z += g_bias[n4 + 2]; s.w += g_bias[n4 + 3];
    ((float4*)g_qe)[idx] = s;
    uint2 hv, lv; split4(s, hv, lv);
    ((uint2*)g_qeh)[idx] = hv;
    ((uint2*)g_qel)[idx] = lv;
}

// ---------------- split-K finish: z = slab0 + slab1 --------------------------
__global__ void z_finish()
{
    int idx = blockIdx.x * 256 + threadIdx.x;   // 98304 float4s
    float4 a = ((const float4*)g_zP)[idx];
    float4 b = ((const float4*)g_zP)[512 * H / 4 + idx];
    a.x += b.x; a.y += b.y; a.z += b.z; a.w += b.w;
    ((float4*)g_z)[idx] = a;
}

// ---------------- weights: stacked WT pairs + WkN pairs + bias ---------------
__global__ void tsplit_all(const float* __restrict__ Wq, const float* __restrict__ Wk,
                           const float* __restrict__ Wv, const float* __restrict__ bq,
                           const float* __restrict__ bk, const float* __restrict__ bv)
{
    int idx = blockIdx.x * 256 + threadIdx.x;
    if (idx < 1280 * H) {
        const float* W; int Nn, nbase, local;
        if (idx < NE * H)            { W = Wq; Nn = NE; nbase = 0;   local = idx; }
        else if (idx < 2 * NE * H)   { W = Wk; Nn = NE; nbase = 256; local = idx - NE * H; }
        else                         { W = Wv; Nn = H;  nbase = 512; local = idx - 2 * NE * H; }
        int k = local / Nn, n = local - k * Nn;
        float x = W[local];                       // coalesced read
        __nv_bfloat16 h = __float2bfloat16(x);
        int oi = (nbase + n) * H + k;             // transposed scatter store
        g_Wh[oi] = h;
        g_Wl[oi] = __float2bfloat16(x - __bfloat162float(h));
    } else if (idx < 1280 * H + H * NE) {
        int local = idx - 1280 * H;
        float x = Wk[local];
        __nv_bfloat16 h = __float2bfloat16(x);
        g_WkNh[local] = h;
        g_WkNl[local] = __float2bfloat16(x - __bfloat162float(h));
    } else if (idx < 1280 * H + H * NE + 1280) {
        int j = idx - 1280 * H - H * NE;
        g_bias[j] = (j < 256) ? bq[j] : (j < 512) ? bk[j - 256] : bv[j - 512];
    }
}

// ---------------- gather + split region rows for qe GEMM ---------------------
__global__ void sgat_kernel(const float* __restrict__ xs)
{
    int idx = blockIdx.x * 256 + threadIdx.x;
    int m = idx / (H / 4), r4 = idx - m * (H / 4);
    int br = m >> 8, b = (m >> 3) & 31, l = m & 7;
    float4 v = ((const float4*)(xs + ((long long)b * S + (br ? 20 : 1) + l) * H))[r4];
    uint2 hv, lv; split4(v, hv, lv);
    ((uint2*)g_qAh)[idx] = hv;
    ((uint2*)g_qAl)[idx] = lv;
}

// ---------------- c[row] = qe[row]·bk ----------------------------------------
__global__ void c_kernel()
{
    int row = blockIdx.x * 8 + (threadIdx.x >> 5);
    int lane = threadIdx.x & 31;
    float p = 0.f;
#pragma unroll
    for (int i = 0; i < 8; i++) {
        int e = lane + i * 32;
        p += g_qe[row * NE + e] * g_bias[256 + e];
    }
#pragma unroll
    for (int o = 16; o > 0; o >>= 1) p += __shfl_xor_sync(0xffffffffu, p, o);
    if (lane == 0) g_c[row] = p;
}

// ---------------- u = Wa @ Wattn halves; cbase -------------------------------
__global__ void u_kernel(const float* __restrict__ Wa, const float* __restrict__ Wattn,
                         const float* __restrict__ ba, const float* __restrict__ battn)
{
    if (blockIdx.x < 48) {
        int gt = blockIdx.x * 256 + threadIdx.x;
        int g = gt >> 3, sub = gt & 7;
        int j = g / H, h = g - j * H;
        float acc = 0.f;
#pragma unroll 4
        for (int a = sub; a < AE; a += 8) acc += Wa[h * AE + a] * Wattn[j * AE + a];
        acc += __shfl_down_sync(0xffffffffu, acc, 4, 8);
        acc += __shfl_down_sync(0xffffffffu, acc, 2, 8);
        acc += __shfl_down_sync(0xffffffffu, acc, 1, 8);
        if (sub == 0) g_u[g] = acc;
    } else {
        __shared__ float red[256];
        int tid = threadIdx.x;
        float v = 0.f;
        if (tid < AE) v = ba[tid] * (Wattn[tid] + Wattn[AE + tid]);
        red[tid] = v; __syncthreads();
        for (int s2 = 128; s2 > 0; s2 >>= 1) {
            if (tid < s2) red[tid] += red[tid + s2];
            __syncthreads();
        }
        if (tid == 0) g_u[2 * H] = red[0] + battn[0];
    }
}

// ---------------- per-(br,b,n): scores from z -> softmax -> message ----------
// Score phase: thread = (t, h-slice); e-slice hoisted to registers, reused
// across all 8 l (z reads broadcast). Partial dots reduced via red[] (aliases
// es). Message phase: thread = h4, 8 accumulators; each emb float4 read once;
// aw transposed so per-t2 weights are 2 broadcast LDS.128.
__global__ __launch_bounds__(256) void neigh_kernel(
    const float* __restrict__ e1, const float* __restrict__ e2)
{
    __shared__ float zs[RL * H];        // 24 KB
    __shared__ float es[T * 196];       // 24.5 KB (chunk Hc=192, stride 196)
    __shared__ float awT[T * 8];        // [t][l]
    __shared__ float cs[RL];
    float* red = es;                    // 8 x 256 reduction buffer (aliases es)

    int br = blockIdx.x >> 10;
    int b = (blockIdx.x >> 5) & 31, n = blockIdx.x & 31;
    int tid = threadIdx.x;
    const float* emb = (br ? e2 : e1) + (long long)(b * NN + n) * T * H;
    const float4* eb4 = (const float4*)emb;

    const float4* z4 = (const float4*)(g_z + (long long)(br * 256 + b * 8) * H);
#pragma unroll
    for (int it = 0; it < 6; it++) {
        int i = it * 256 + tid;
        *(float4*)&zs[i * 4] = z4[i];
    }
    if (tid < 8) cs[tid] = g_c[br * 256 + b * 8 + tid];
    __syncthreads();

    // ---- score phase: thread (tt = tid&31, sh = tid>>5) ----
    const int tt = tid & 31, sh = tid >> 5;
    float acc8[8];
#pragma unroll
    for (int l = 0; l < 8; l++) acc8[l] = 0.f;

#pragma unroll
    for (int ch = 0; ch < 4; ch++) {
        for (int i = tid; i < T * 48; i += 256) {
            int t2 = i / 48, h4 = i - t2 * 48;
            *(float4*)&es[t2 * 196 + h4 * 4] = eb4[t2 * (H / 4) + ch * 48 + h4];
        }
        __syncthreads();
        const float4* er = (const float4*)&es[tt * 196 + sh * 24];
        float4 ev[6];
#pragma unroll
        for (int j = 0; j < 6; j++) ev[j] = er[j];
#pragma unroll
        for (int l = 0; l < 8; l++) {
            const float4* zr = (const float4*)&zs[l * H + ch * 192 + sh * 24];
            float a = 0.f;
#pragma unroll
            for (int j = 0; j < 6; j++) {
                float4 zv = zr[j];
                a += ev[j].x * zv.x + ev[j].y * zv.y + ev[j].z * zv.z + ev[j].w * zv.w;
            }
            acc8[l] += a;
        }
        __syncthreads();
    }

    // reduce partial dots across the 8 h-slices (red aliases es — safe: all
    // es reads done, guarded by the trailing sync of the chunk loop)
#pragma unroll
    for (int l = 0; l < 8; l++) red[sh * 256 + l * 32 + tt] = acc8[l];
    __syncthreads();

    const int l = tid >> 5;   // softmax layout: warp = l, lane = t
    float s = 0.f;
#pragma unroll
    for (int k = 0; k < 8; k++) s += red[k * 256 + tid];
    s = (s + cs[l]) * SCALE;
    float m = s;
#pragma unroll
    for (int o = 16; o > 0; o >>= 1) m = fmaxf(m, __shfl_xor_sync(0xffffffffu, m, o));
    float ex = __expf(s - m), sum = ex;
#pragma unroll
    for (int o = 16; o > 0; o >>= 1) sum += __shfl_xor_sync(0xffffffffu, sum, o);
    awT[tt * 8 + l] = ex / sum;
    __syncthreads();

    // ---- message phase: thread = h4 (192 active), 8 accumulators ----
    if (tid < H / 4) {
        const int h4 = tid;
        float4 mac[8];
#pragma unroll
        for (int l2 = 0; l2 < 8; l2++) mac[l2] = make_float4(0.f, 0.f, 0.f, 0.f);
        for (int t2 = 0; t2 < T; t2++) {
            float4 e = eb4[t2 * (H / 4) + h4];
            float4 w0 = *(const float4*)&awT[t2 * 8];
            float4 w1 = *(const float4*)&awT[t2 * 8 + 4];
            float wv[8] = {w0.x, w0.y, w0.z, w0.w, w1.x, w1.y, w1.z, w1.w};
#pragma unroll
            for (int l2 = 0; l2 < 8; l2++) {
                mac[l2].x += wv[l2] * e.x; mac[l2].y += wv[l2] * e.y;
                mac[l2].z += wv[l2] * e.z; mac[l2].w += wv[l2] * e.w;
            }
        }
        float4* mb4 = (float4*)((br ? g_msg2 : g_msg1) + (long long)(b * NN + n) * RL * H);
#pragma unroll
        for (int l2 = 0; l2 < 8; l2++) mb4[l2 * (H / 4) + h4] = mac[l2];
    }
}

// ---------------- region gate dots -------------------------------------------
__global__ __launch_bounds__(128) void rscore_kernel(
    const float* __restrict__ xs, const float* __restrict__ msg1,
    const float* __restrict__ msg2)
{
    __shared__ float wred[4];
    int id = blockIdx.x;
    int br = id / (Bn * 33);
    int rem = id - br * (Bn * 33);
    int b = rem / 33, j = rem - b * 33;
    int tid = threadIdx.x;

    const float* src;
    const float* uvec;
    if (j < NN) {
        src = (br ? msg2 : msg1) + (long long)(b * NN + j) * RL * H;
        uvec = g_u + H;
    } else {
        src = xs + ((long long)b * S + (br ? 20 : 1)) * H;
        uvec = g_u;
    }
    const float4* s4 = (const float4*)src;
    float p = 0.f;
#pragma unroll
    for (int it = 0; it < RL * H / 4 / 128; it++) {
        int i = it * 128 + tid;
        float4 v = s4[i];
        const float* up = uvec + (i % (H / 4)) * 4;
        p += v.x * up[0] + v.y * up[1] + v.z * up[2] + v.w * up[3];
    }
#pragma unroll
    for (int o = 16; o > 0; o >>= 1) p += __shfl_xor_sync(0xffffffffu, p, o);
    if ((tid & 31) == 0) wred[tid >> 5] = p;
    __syncthreads();
    if (tid == 0) {
        float tot = (wred[0] + wred[1] + wred[2] + wred[3]) * (1.f / RL);
        if (j < NN) g_md[(br * Bn + b) * NN + j] = tot;
        else        g_feas[br * Bn + b] = tot;
    }
}

__global__ void rsoftmax_kernel(const float* __restrict__ dist1,
                                const float* __restrict__ dist2,
                                const float* __restrict__ wb,
                                const float* __restrict__ bb)
{
    int br = blockIdx.x >> 5, b = blockIdx.x & 31;
    int lane = threadIdx.x;
    float pre = g_feas[br * Bn + b] + g_md[(br * Bn + b) * NN + lane] + g_u[2 * H];
    float z = pre >= 0.f ? pre : NEG * pre;
    const float* dist = br ? dist2 : dist1;
    float v = z + dist[b * NN + lane] * wb[0] + bb[0];
    float m = v;
#pragma unroll
    for (int o = 16; o > 0; o >>= 1) m = fmaxf(m, __shfl_xor_sync(0xffffffffu, m, o));
    float e = __expf(v - m), s = e;
#pragma unroll
    for (int o = 16; o > 0; o >>= 1) s += __shfl_xor_sync(0xffffffffu, s, o);
    (br ? g_att2 : g_att1)[b * NN + lane] = e / s;
}

// ---------------- x = xs (+ gated messages) -> bf16 pairs --------------------
__global__ void build_x_kernel(const float* __restrict__ xs)
{
    int idx = blockIdx.x * 256 + threadIdx.x;
    float4 v = ((const float4*)xs)[idx];
    int h4 = idx % (H / 4);
    int s = (idx / (H / 4)) % S;
    int b = idx / (S * H / 4);
    if (s >= 1 && s < 9) {
        int l = s - 1;
        const float4* m4 = (const float4*)g_msg1;
#pragma unroll 4
        for (int n = 0; n < NN; n++) {
            float a = g_att1[b * NN + n];
            float4 m = m4[((b * NN + n) * RL + l) * (H / 4) + h4];
            v.x += a * m.x; v.y += a * m.y; v.z += a * m.z; v.w += a * m.w;
        }
    } else if (s >= 20 && s < 28) {
        int l = s - 20;
        const float4* m4 = (const float4*)g_msg2;
#pragma unroll 4
        for (int n = 0; n < NN; n++) {
            float a = g_att2[b * NN + n];
            float4 m = m4[((b * NN + n) * RL + l) * (H / 4) + h4];
            v.x += a * m.x; v.y += a * m.y; v.z += a * m.z; v.w += a * m.w;
        }
    }
    uint2 hv, lv; split4(v, hv, lv);
    ((uint2*)g_xh)[idx] = hv;
    ((uint2*)g_xl)[idx] = lv;
}

// ---------------- row softmax (warp/row) -> bf16 pairs -----------------------
__global__ __launch_bounds__(256) void softmax_rows_kernel()
{
    int warp = threadIdx.x >> 5, lane = threadIdx.x & 31;
    long long row = (long long)blockIdx.x * 8 + warp;
    const float4* r4 = (const float4*)(g_probs + row * S);
    float4 x[4];
    float m = -3.4e38f;
#pragma unroll
    for (int k = 0; k < 4; k++) {
        x[k] = r4[lane + 32 * k];
        m = fmaxf(m, fmaxf(fmaxf(x[k].x, x[k].y), fmaxf(x[k].z, x[k].w)));
    }
#pragma unroll
    for (int o = 16; o > 0; o >>= 1) m = fmaxf(m, __shfl_xor_sync(0xffffffffu, m, o));
    float s = 0.f;
#pragma unroll
    for (int k = 0; k < 4; k++) {
        x[k].x = __expf(x[k].x - m); x[k].y = __expf(x[k].y - m);
        x[k].z = __expf(x[k].z - m); x[k].w = __expf(x[k].w - m);
        s += x[k].x + x[k].y + x[k].z + x[k].w;
    }
#pragma unroll
    for (int o = 16; o > 0; o >>= 1) s += __shfl_xor_sync(0xffffffffu, s, o);
    float inv = 1.f / s;
    uint2* ph4 = (uint2*)(g_ph + row * S);
    uint2* pl4 = (uint2*)(g_pl + row * S);
#pragma unroll
    for (int k = 0; k < 4; k++) {
        x[k].x *= inv; x[k].y *= inv; x[k].z *= inv; x[k].w *= inv;
        uint2 hv, lv; split4(x[k], hv, lv);
        ph4[lane + 32 * k] = hv;
        pl4[lane + 32 * k] = lv;
    }
}

// ---------------- launch ----------------
extern "C" void kernel_launch(void* const* d_in, const int* in_sizes, int n_in,
                              void* d_out, int out_size)
{
    const float* xs    = (const float*)d_in[0];
    const float* n1emb = (const float*)d_in[1];
    const float* n2emb = (const float*)d_in[2];
    const float* dist1 = (const float*)d_in[3];
    const float* dist2 = (const float*)d_in[4];
    const float* Wq    = (const float*)d_in[5];
    const float* bq    = (const float*)d_in[6];
    const float* Wk    = (const float*)d_in[7];
    const float* bk    = (const float*)d_in[8];
    const float* Wv    = (const float*)d_in[9];
    const float* bv    = (const float*)d_in[10];
    const float* Wa    = (const float*)d_in[11];
    const float* ba    = (const float*)d_in[12];
    const float* Wattn = (const float*)d_in[13];
    const float* battn = (const float*)d_in[14];
    const float* wb    = (const float*)d_in[15];
    const float* bb    = (const float*)d_in[16];
    float* out = (float*)d_out;

    float *pp, *pm1, *pm2, *pqeP, *pzP, *pbias;
    __nv_bfloat16 *pwh, *pwl, *pwknh, *pwknl, *pqeh, *pqel, *pxh, *pxl,
                  *pqkh, *pqkl, *pvh, *pvl, *pph, *ppl, *pah, *pal;
    cudaGetSymbolAddress((void**)&pp,    g_probs);
    cudaGetSymbolAddress((void**)&pm1,   g_msg1);
    cudaGetSymbolAddress((void**)&pm2,   g_msg2);
    cudaGetSymbolAddress((void**)&pqeP,  g_qeP);
    cudaGetSymbolAddress((void**)&pzP,   g_zP);
    cudaGetSymbolAddress((void**)&pbias, g_bias);
    cudaGetSymbolAddress((void**)&pwh,   g_Wh);
    cudaGetSymbolAddress((void**)&pwl,   g_Wl);
    cudaGetSymbolAddress((void**)&pwknh, g_WkNh);
    cudaGetSymbolAddress((void**)&pwknl, g_WkNl);
    cudaGetSymbolAddress((void**)&pqeh,  g_qeh);
    cudaGetSymbolAddress((void**)&pqel,  g_qel);
    cudaGetSymbolAddress((void**)&pxh,   g_xh);
    cudaGetSymbolAddress((void**)&pxl,   g_xl);
    cudaGetSymbolAddress((void**)&pqkh,  g_qkh);
    cudaGetSymbolAddress((void**)&pqkl,  g_qkl);
    cudaGetSymbolAddress((void**)&pvh,   g_vTh);
    cudaGetSymbolAddress((void**)&pvl,   g_vTl);
    cudaGetSymbolAddress((void**)&pph,   g_ph);
    cudaGetSymbolAddress((void**)&ppl,   g_pl);
    cudaGetSymbolAddress((void**)&pah,   g_qAh);
    cudaGetSymbolAddress((void**)&pal,   g_qAl);

    cudaFuncSetAttribute(bgemm<0, false>, cudaFuncAttributeMaxDynamicSharedMemorySize, BG_SMEM);
    cudaFuncSetAttribute(bgemm<0, true>,  cudaFuncAttributeMaxDynamicSharedMemorySize, BG_SMEM);
    cudaFuncSetAttribute(bgemm<3, false>, cudaFuncAttributeMaxDynamicSharedMemorySize, BG_SMEM);

    // prep
    tsplit_all<<<(1280 * H + H * NE + 1280 + 255) / 256, 256>>>(Wq, Wk, Wv, bq, bk, bv);
    u_kernel<<<49, 256>>>(Wa, Wattn, ba, battn);
    sgat_kernel<<<512 * (H / 4) / 256, 256>>>(xs);

    // qe slabs: split-K 6 x 128 over K=768  (grid 2x4x6 = 48 CTAs)
    bgemm<0, true><<<dim3(2, 4, 6), 256, BG_SMEM>>>(
        pah, pal, pwh, pwl, nullptr, pqeP, nullptr, nullptr, nullptr, nullptr,
        H, H, NE, 128, 1.f, 0, 0, (long long)512 * NE);
    qe_finish<<<128, 256>>>();

    // z slabs: split-K 2 x 128 over K=256 (grid 6x4x2 = 48 CTAs)
    bgemm<0, true><<<dim3(6, 4, 2), 256, BG_SMEM>>>(
        pqeh, pqel, pwknh, pwknl, nullptr, pzP, nullptr, nullptr, nullptr, nullptr,
        NE, NE, H, 128, 1.f, 0, 0, (long long)512 * H);
    z_finish<<<384, 256>>>();
    c_kernel<<<64, 256>>>();

    // neighbor attention via emb·z + messages (both branches)
    neigh_kernel<<<2 * Bn * NN, 256>>>(n1emb, n2emb);

    // gate attention + x pairs
    rscore_kernel<<<2 * Bn * 33, 128>>>(xs, pm1, pm2);
    rsoftmax_kernel<<<2 * Bn, 32>>>(dist1, dist2, wb, bb);
    build_x_kernel<<<(Bn * S * H / 4) / 256, 256>>>(xs);

    // fused q/k/v projections: M = 16384 -> 128 M-tiles, N = 1280 -> 10 N-tiles
    bgemm<3, false><<<dim3(10, 128, 1), 256, BG_SMEM>>>(
        pxh, pxl, pwh, pwl, pbias, nullptr, pqkh, pqkl, pvh, pvl,
        H, H, 512, H, 1.f, 0, 0, 0);

    // scores = SCALE * q @ k^T (batched, grid 4x4x32 = 512)
    bgemm<0, false><<<dim3(4, 4, 32), 256, BG_SMEM>>>(
        pqkh, pqkl, pqkh + 256, pqkl + 256, nullptr, pp,
        nullptr, nullptr, nullptr, nullptr,
        512, 512, S, NE, SCALE,
        (long long)S * 512, (long long)S * 512, (long long)S * S);

    softmax_rows_kernel<<<Bn * S / 8, 256>>>();

    // out = probs @ v (batched, grid 6x4x32 = 768)
    bgemm<0, false><<<dim3(6, 4, 32), 256, BG_SMEM>>>(
        pph, ppl, pvh, pvl, nullptr, out, nullptr, nullptr, nullptr, nullptr,
        512, 512, H, S, 1.f,
        (long long)S * S, (long long)H * S, (long long)S * H);
}

// round 15
// speedup vs baseline: 1.0618x; 1.0089x over previous
#include <cuda_runtime.h>
#include <cuda_bf16.h>
#include <cstdint>

// ---------------- problem constants ----------------
namespace {
constexpr int Bn = 32;
constexpr int S  = 512;
constexpr int H  = 768;
constexpr int NN = 32;
constexpr int T  = 32;
constexpr int NE = 256;
constexpr int AE = 128;
constexpr int RL = 8;
constexpr float SCALE = 0.0625f;
constexpr float NEG   = 0.01f;
}

// ---------------- scratch ----------------
__device__ float g_probs[Bn * S * S];
__device__ float g_msg1 [Bn * NN * RL * H];
__device__ float g_msg2 [Bn * NN * RL * H];
__device__ float g_qe   [2 * Bn * RL * NE];
__device__ float g_qeP  [6 * 512 * NE];         // split-K partial slabs
__device__ float g_z    [2 * Bn * RL * H];
__device__ float g_zP   [2 * 512 * H];
__device__ float g_c    [2 * Bn * RL];
__device__ float g_att1 [Bn * NN];
__device__ float g_att2 [Bn * NN];
__device__ float g_u    [2 * H + 1];
__device__ float g_md   [2 * Bn * NN];
__device__ float g_feas [2 * Bn];
__device__ float g_bias [1280];

__device__ __nv_bfloat16 g_Wh  [1280 * H], g_Wl  [1280 * H];  // stacked WqT|WkT|WvT
__device__ __nv_bfloat16 g_WkNh[H * NE],   g_WkNl[H * NE];    // Wk original layout
__device__ __nv_bfloat16 g_qeh [512 * NE], g_qel [512 * NE];
__device__ __nv_bfloat16 g_xh  [Bn * S * H], g_xl [Bn * S * H];
__device__ __nv_bfloat16 g_qkh [Bn * S * 512], g_qkl[Bn * S * 512];
__device__ __nv_bfloat16 g_vTh [Bn * H * S], g_vTl[Bn * H * S];
__device__ __nv_bfloat16 g_ph  [Bn * S * S], g_pl [Bn * S * S];
__device__ __nv_bfloat16 g_qAh [512 * H],   g_qAl [512 * H];

// ---------------- helpers ----------------
__device__ __forceinline__ uint32_t smem_u32(const void* p) {
    uint32_t a;
    asm("{ .reg .u64 t; cvta.to.shared.u64 t, %1; cvt.u32.u64 %0, t; }" : "=r"(a) : "l"(p));
    return a;
}
__device__ __forceinline__ uint32_t bpack(__nv_bfloat16 a, __nv_bfloat16 b) {
    __nv_bfloat162 t = __halves2bfloat162(a, b);
    return *reinterpret_cast<uint32_t*>(&t);
}
__device__ __forceinline__ uint32_t fpack(float a, float b) {
    __nv_bfloat162 t = __floats2bfloat162_rn(a, b);
    return *reinterpret_cast<uint32_t*>(&t);
}
__device__ __forceinline__ void split4(float4 v, uint2& hv, uint2& lv) {
    __nv_bfloat16 h0 = __float2bfloat16(v.x), h1 = __float2bfloat16(v.y);
    __nv_bfloat16 h2 = __float2bfloat16(v.z), h3 = __float2bfloat16(v.w);
    hv.x = bpack(h0, h1); hv.y = bpack(h2, h3);
    lv.x = fpack(v.x - __bfloat162float(h0), v.y - __bfloat162float(h1));
    lv.y = fpack(v.z - __bfloat162float(h2), v.w - __bfloat162float(h3));
}
__device__ __forceinline__ void ldsm4(uint32_t& r0, uint32_t& r1, uint32_t& r2,
                                      uint32_t& r3, uint32_t a) {
    asm volatile("ldmatrix.sync.aligned.m8n8.x4.shared.b16 {%0,%1,%2,%3}, [%4];"
                 : "=r"(r0), "=r"(r1), "=r"(r2), "=r"(r3) : "r"(a));
}
__device__ __forceinline__ void mma16816(float* d, const uint32_t* a, const uint32_t* b) {
    asm volatile(
        "mma.sync.aligned.m16n8k16.row.col.f32.bf16.bf16.f32 "
        "{%0,%1,%2,%3}, {%4,%5,%6,%7}, {%8,%9}, {%0,%1,%2,%3};"
        : "+f"(d[0]), "+f"(d[1]), "+f"(d[2]), "+f"(d[3])
        : "r"(a[0]), "r"(a[1]), "r"(a[2]), "r"(a[3]), "r"(b[0]), "r"(b[1]));
}

// ================= all-bf16 cp.async bf16x3 GEMM, CTA 128x128 =================
// 8 warps (2x4), warp tile 64x32, BK=32, 2-stage pipeline, 2 CTAs/SM.
// Inner loop: mt outermost with per-mt A-fragment loads to keep regs <= 128.
// EPI 0: fp32 out.  EPI 3: qkv routing (qk pairs / v SMEM-transposed pairs).
// SK: blockIdx.z = K-slice (length K); output slab at Cf + bz*sC.
constexpr int ROWB  = 80;
constexpr int MTILE = 128 * ROWB;     // 10240
constexpr int STG   = 4 * MTILE;      // 40960
constexpr int BG_SMEM = 2 * STG;      // 81920 -> 2 CTAs/SM

template<int EPI, bool SK>
__global__ __launch_bounds__(256, 2) void bgemm(
    const __nv_bfloat16* __restrict__ Ahp, const __nv_bfloat16* __restrict__ Alp,
    const __nv_bfloat16* __restrict__ Bhp, const __nv_bfloat16* __restrict__ Blp,
    const float* __restrict__ bias, float* __restrict__ Cf,
    __nv_bfloat16* __restrict__ Ch, __nv_bfloat16* __restrict__ Cl,
    __nv_bfloat16* __restrict__ Dh, __nv_bfloat16* __restrict__ Dl,
    int lda, int ldb, int ldc, int K, float alpha,
    long long sA, long long sB, long long sC)
{
    extern __shared__ char smem[];
    const uint32_t sb = smem_u32(smem);
    const int tid = threadIdx.x, w = tid >> 5, lane = tid & 31;
    const int m0 = blockIdx.y * 128, n0 = blockIdx.x * 128, bz = blockIdx.z;
    int koff = 0;
    if (SK) {
        koff = bz * K;
        Cf += bz * sC;
    } else {
        Ahp += bz * sA; Alp += bz * sA;
        Bhp += bz * sB; Blp += bz * sB;
        if (EPI == 0) Cf += bz * sC;
    }

    const int wm = (w >> 2) * 64, wn = (w & 3) * 32;
    float acc[4][4][4];
#pragma unroll
    for (int a = 0; a < 4; a++)
#pragma unroll
        for (int b = 0; b < 4; b++)
#pragma unroll
            for (int c = 0; c < 4; c++) acc[a][b][c] = 0.f;

    const int nch = K >> 5;   // BK = 32

    auto issue = [&](int c) {
        if (c < nch) {
            const int k0 = (c << 5) + koff;
            const uint32_t dstb = sb + (c & 1) * STG;
#pragma unroll
            for (int mat = 0; mat < 4; mat++) {
                const __nv_bfloat16* g = (mat == 0) ? Ahp : (mat == 1) ? Alp
                                       : (mat == 2) ? Bhp : Blp;
                const int rb = (mat < 2) ? m0 : n0;
                const int ld = (mat < 2) ? lda : ldb;
#pragma unroll
                for (int it = 0; it < 2; it++) {
                    int i = (it << 8) + tid, row = i >> 2, c16 = i & 3;
                    const __nv_bfloat16* src = g + (long long)(rb + row) * ld + k0 + (c16 << 3);
                    asm volatile("cp.async.cg.shared.global [%0], [%1], 16;"
                                 :: "r"(dstb + mat * MTILE + row * ROWB + (c16 << 4)), "l"(src));
                }
            }
        }
        asm volatile("cp.async.commit_group;");
    };

    const int q = lane >> 3, r = lane & 7;
    const int aRow = ((q & 1) << 3) + r;
    const int aCol = (q >> 1) << 4;
    const int bRow = ((q >> 1) << 3) + r;
    const int bCol = (q & 1) << 4;

    auto compute = [&](int c) {
        const uint32_t Ah = sb + (c & 1) * STG;
        const uint32_t Al = Ah + MTILE, Bh = Ah + 2 * MTILE, Bl = Ah + 3 * MTILE;
#pragma unroll
        for (int s = 0; s < 2; s++) {
            const int kOff = s * 32;
            uint32_t bh[4][2], bl[4][2];
#pragma unroll
            for (int np = 0; np < 2; np++) {
                uint32_t off = (uint32_t)(wn + np * 16 + bRow) * ROWB + kOff + bCol;
                ldsm4(bh[2 * np][0], bh[2 * np][1],
                      bh[2 * np + 1][0], bh[2 * np + 1][1], Bh + off);
                ldsm4(bl[2 * np][0], bl[2 * np][1],
                      bl[2 * np + 1][0], bl[2 * np + 1][1], Bl + off);
            }
#pragma unroll
            for (int mt = 0; mt < 4; mt++) {
                uint32_t ah[4], al[4];
                uint32_t off = (uint32_t)(wm + mt * 16 + aRow) * ROWB + kOff + aCol;
                ldsm4(ah[0], ah[1], ah[2], ah[3], Ah + off);
                ldsm4(al[0], al[1], al[2], al[3], Al + off);
#pragma unroll
                for (int nt = 0; nt < 4; nt++) {
                    mma16816(acc[mt][nt], ah, bh[nt]);
                    mma16816(acc[mt][nt], ah, bl[nt]);
                    mma16816(acc[mt][nt], al, bh[nt]);
                }
            }
        }
    };

    issue(0); issue(1);
    for (int c = 0; c < nch; c++) {
        asm volatile("cp.async.wait_group 1;");
        __syncthreads();
        compute(c);
        __syncthreads();
        issue(c + 2);
    }

    const int gid = lane >> 2, tig = lane & 3;

    if (EPI == 3 && n0 >= 512) {
        // v tile: transpose through SMEM (67.6 KB fits the 80 KB buffer),
        // then coalesced bf16 pair stores.
        float* st = (float*)smem;   // [n][m], stride 132
        __syncthreads();
#pragma unroll
        for (int mt = 0; mt < 4; mt++)
#pragma unroll
            for (int half = 0; half < 2; half++) {
                const int m = wm + mt * 16 + gid + half * 8;
#pragma unroll
                for (int nt = 0; nt < 4; nt++) {
                    const int n = wn + nt * 8 + tig * 2;
                    st[n * 132 + m]       = acc[mt][nt][half * 2 + 0] + bias[n0 + n];
                    st[(n + 1) * 132 + m] = acc[mt][nt][half * 2 + 1] + bias[n0 + n + 1];
                }
            }
        __syncthreads();
        const long long bb2 = m0 >> 9;
        const int t0 = m0 & 511, nvb = n0 - 512;
#pragma unroll
        for (int it = 0; it < 32; it++) {
            int i = it * 256 + tid;
            int n = i >> 6, mc = (i & 63) << 1;
            float v0 = st[n * 132 + mc], v1 = st[n * 132 + mc + 1];
            __nv_bfloat16 h0 = __float2bfloat16(v0), h1 = __float2bfloat16(v1);
            long long gi = (bb2 * 768 + nvb + n) * 512 + t0 + mc;
            *(uint32_t*)&Dh[gi] = bpack(h0, h1);
            *(uint32_t*)&Dl[gi] =
                fpack(v0 - __bfloat162float(h0), v1 - __bfloat162float(h1));
        }
    } else {
#pragma unroll
        for (int mt = 0; mt < 4; mt++)
#pragma unroll
            for (int half = 0; half < 2; half++) {
                const long long m = m0 + wm + mt * 16 + gid + half * 8;
#pragma unroll
                for (int nt = 0; nt < 4; nt++) {
                    float v0 = acc[mt][nt][half * 2 + 0];
                    float v1 = acc[mt][nt][half * 2 + 1];
                    const int n = n0 + wn + nt * 8 + tig * 2;
                    if (EPI == 0) {
                        v0 *= alpha; v1 *= alpha;
                        if (bias) { v0 += bias[n]; v1 += bias[n + 1]; }
                        *(float2*)&Cf[m * ldc + n] = make_float2(v0, v1);
                    } else {  // EPI == 3, qk half
                        v0 += bias[n]; v1 += bias[n + 1];
                        __nv_bfloat16 h0 = __float2bfloat16(v0), h1 = __float2bfloat16(v1);
                        *(uint32_t*)&Ch[m * 512 + n] = bpack(h0, h1);
                        *(uint32_t*)&Cl[m * 512 + n] =
                            fpack(v0 - __bfloat162float(h0), v1 - __bfloat162float(h1));
                    }
                }
            }
    }
}

// ---------------- split-K finish: qe = sum(slabs) + bq; emit fp32 + pairs ----
__global__ void qe_finish()
{
    int idx = blockIdx.x * 256 + threadIdx.x;   // 32768 float4s
    int n4 = (idx % (NE / 4)) * 4;
    float4 s = ((const float4*)g_qeP)[idx];
#pragma unroll
    for (int k = 1; k < 6; k++) {
        float4 p = ((const float4*)g_qeP)[k * (512 * NE / 4) + idx];
        s.x += p.x; s.y += p.y; s.z += p.z; s.w += p.w;
    }
    s.x += g_bias[n4]; s.y += g_bias[n4 + 1];
    s.z += g_bias[n4 + 2]; s.w += g_bias[n4 + 3];
    ((float4*)g_qe)[idx] = s;
    uint2 hv, lv; split4(s, hv, lv);
    ((uint2*)g_qeh)[idx] = hv;
    ((uint2*)g_qel)[idx] = lv;
}

// ---------------- split-K finish: z = slab0 + slab1 --------------------------
__global__ void z_finish()
{
    int idx = blockIdx.x * 256 + threadIdx.x;   // 98304 float4s
    float4 a = ((const float4*)g_zP)[idx];
    float4 b = ((const float4*)g_zP)[512 * H / 4 + idx];
    a.x += b.x; a.y += b.y; a.z += b.z; a.w += b.w;
    ((float4*)g_z)[idx] = a;
}

// ---------------- weights: stacked WT pairs + WkN pairs + bias ---------------
__global__ void tsplit_all(const float* __restrict__ Wq, const float* __restrict__ Wk,
                           const float* __restrict__ Wv, const float* __restrict__ bq,
                           const float* __restrict__ bk, const float* __restrict__ bv)
{
    int idx = blockIdx.x * 256 + threadIdx.x;
    if (idx < 1280 * H) {
        const float* W; int Nn, nbase, local;
        if (idx < NE * H)            { W = Wq; Nn = NE; nbase = 0;   local = idx; }
        else if (idx < 2 * NE * H)   { W = Wk; Nn = NE; nbase = 256; local = idx - NE * H; }
        else                         { W = Wv; Nn = H;  nbase = 512; local = idx - 2 * NE * H; }
        int k = local / Nn, n = local - k * Nn;
        float x = W[local];                       // coalesced read
        __nv_bfloat16 h = __float2bfloat16(x);
        int oi = (nbase + n) * H + k;             // transposed scatter store
        g_Wh[oi] = h;
        g_Wl[oi] = __float2bfloat16(x - __bfloat162float(h));
    } else if (idx < 1280 * H + H * NE) {
        int local = idx - 1280 * H;
        float x = Wk[local];
        __nv_bfloat16 h = __float2bfloat16(x);
        g_WkNh[local] = h;
        g_WkNl[local] = __float2bfloat16(x - __bfloat162float(h));
    } else if (idx < 1280 * H + H * NE + 1280) {
        int j = idx - 1280 * H - H * NE;
        g_bias[j] = (j < 256) ? bq[j] : (j < 512) ? bk[j - 256] : bv[j - 512];
    }
}

// ---------------- gather + split region rows for qe GEMM ---------------------
__global__ void sgat_kernel(const float* __restrict__ xs)
{
    int idx = blockIdx.x * 256 + threadIdx.x;
    int m = idx / (H / 4), r4 = idx - m * (H / 4);
    int br = m >> 8, b = (m >> 3) & 31, l = m & 7;
    float4 v = ((const float4*)(xs + ((long long)b * S + (br ? 20 : 1) + l) * H))[r4];
    uint2 hv, lv; split4(v, hv, lv);
    ((uint2*)g_qAh)[idx] = hv;
    ((uint2*)g_qAl)[idx] = lv;
}

// ---------------- c[row] = qe[row]·bk ----------------------------------------
__global__ void c_kernel()
{
    int row = blockIdx.x * 8 + (threadIdx.x >> 5);
    int lane = threadIdx.x & 31;
    float p = 0.f;
#pragma unroll
    for (int i = 0; i < 8; i++) {
        int e = lane + i * 32;
        p += g_qe[row * NE + e] * g_bias[256 + e];
    }
#pragma unroll
    for (int o = 16; o > 0; o >>= 1) p += __shfl_xor_sync(0xffffffffu, p, o);
    if (lane == 0) g_c[row] = p;
}

// ---------------- u = Wa @ Wattn halves; cbase -------------------------------
__global__ void u_kernel(const float* __restrict__ Wa, const float* __restrict__ Wattn,
                         const float* __restrict__ ba, const float* __restrict__ battn)
{
    if (blockIdx.x < 48) {
        int gt = blockIdx.x * 256 + threadIdx.x;
        int g = gt >> 3, sub = gt & 7;
        int j = g / H, h = g - j * H;
        float acc = 0.f;
#pragma unroll 4
        for (int a = sub; a < AE; a += 8) acc += Wa[h * AE + a] * Wattn[j * AE + a];
        acc += __shfl_down_sync(0xffffffffu, acc, 4, 8);
        acc += __shfl_down_sync(0xffffffffu, acc, 2, 8);
        acc += __shfl_down_sync(0xffffffffu, acc, 1, 8);
        if (sub == 0) g_u[g] = acc;
    } else {
        __shared__ float red[256];
        int tid = threadIdx.x;
        float v = 0.f;
        if (tid < AE) v = ba[tid] * (Wattn[tid] + Wattn[AE + tid]);
        red[tid] = v; __syncthreads();
        for (int s2 = 128; s2 > 0; s2 >>= 1) {
            if (tid < s2) red[tid] += red[tid + s2];
            __syncthreads();
        }
        if (tid == 0) g_u[2 * H] = red[0] + battn[0];
    }
}

// ---------------- per-(br,b,n): scores from z -> softmax -> message ----------
__global__ __launch_bounds__(256) void neigh_kernel(
    const float* __restrict__ e1, const float* __restrict__ e2)
{
    __shared__ float zs[RL * H];        // 24 KB
    __shared__ float es[T * 196];       // 24.5 KB
    __shared__ float awT[T * 8];        // [t][l]
    __shared__ float cs[RL];
    float* red = es;                    // 8 x 256 reduction buffer (aliases es)

    int br = blockIdx.x >> 10;
    int b = (blockIdx.x >> 5) & 31, n = blockIdx.x & 31;
    int tid = threadIdx.x;
    const float* emb = (br ? e2 : e1) + (long long)(b * NN + n) * T * H;
    const float4* eb4 = (const float4*)emb;

    const float4* z4 = (const float4*)(g_z + (long long)(br * 256 + b * 8) * H);
#pragma unroll
    for (int it = 0; it < 6; it++) {
        int i = it * 256 + tid;
        *(float4*)&zs[i * 4] = z4[i];
    }
    if (tid < 8) cs[tid] = g_c[br * 256 + b * 8 + tid];
    __syncthreads();

    const int tt = tid & 31, sh = tid >> 5;
    float acc8[8];
#pragma unroll
    for (int l = 0; l < 8; l++) acc8[l] = 0.f;

#pragma unroll
    for (int ch = 0; ch < 4; ch++) {
        for (int i = tid; i < T * 48; i += 256) {
            int t2 = i / 48, h4 = i - t2 * 48;
            *(float4*)&es[t2 * 196 + h4 * 4] = eb4[t2 * (H / 4) + ch * 48 + h4];
        }
        __syncthreads();
        const float4* er = (const float4*)&es[tt * 196 + sh * 24];
        float4 ev[6];
#pragma unroll
        for (int j = 0; j < 6; j++) ev[j] = er[j];
#pragma unroll
        for (int l = 0; l < 8; l++) {
            const float4* zr = (const float4*)&zs[l * H + ch * 192 + sh * 24];
            float a = 0.f;
#pragma unroll
            for (int j = 0; j < 6; j++) {
                float4 zv = zr[j];
                a += ev[j].x * zv.x + ev[j].y * zv.y + ev[j].z * zv.z + ev[j].w * zv.w;
            }
            acc8[l] += a;
        }
        __syncthreads();
    }

#pragma unroll
    for (int l = 0; l < 8; l++) red[sh * 256 + l * 32 + tt] = acc8[l];
    __syncthreads();

    const int l = tid >> 5;
    float s = 0.f;
#pragma unroll
    for (int k = 0; k < 8; k++) s += red[k * 256 + tid];
    s = (s + cs[l]) * SCALE;
    float m = s;
#pragma unroll
    for (int o = 16; o > 0; o >>= 1) m = fmaxf(m, __shfl_xor_sync(0xffffffffu, m, o));
    float ex = __expf(s - m), sum = ex;
#pragma unroll
    for (int o = 16; o > 0; o >>= 1) sum += __shfl_xor_sync(0xffffffffu, sum, o);
    awT[tt * 8 + l] = ex / sum;
    __syncthreads();

    if (tid < H / 4) {
        const int h4 = tid;
        float4 mac[8];
#pragma unroll
        for (int l2 = 0; l2 < 8; l2++) mac[l2] = make_float4(0.f, 0.f, 0.f, 0.f);
        for (int t2 = 0; t2 < T; t2++) {
            float4 e = eb4[t2 * (H / 4) + h4];
            float4 w0 = *(const float4*)&awT[t2 * 8];
            float4 w1 = *(const float4*)&awT[t2 * 8 + 4];
            float wv[8] = {w0.x, w0.y, w0.z, w0.w, w1.x, w1.y, w1.z, w1.w};
#pragma unroll
            for (int l2 = 0; l2 < 8; l2++) {
                mac[l2].x += wv[l2] * e.x; mac[l2].y += wv[l2] * e.y;
                mac[l2].z += wv[l2] * e.z; mac[l2].w += wv[l2] * e.w;
            }
        }
        float4* mb4 = (float4*)((br ? g_msg2 : g_msg1) + (long long)(b * NN + n) * RL * H);
#pragma unroll
        for (int l2 = 0; l2 < 8; l2++) mb4[l2 * (H / 4) + h4] = mac[l2];
    }
}

// ---------------- region gate dots -------------------------------------------
__global__ __launch_bounds__(128) void rscore_kernel(
    const float* __restrict__ xs, const float* __restrict__ msg1,
    const float* __restrict__ msg2)
{
    __shared__ float wred[4];
    int id = blockIdx.x;
    int br = id / (Bn * 33);
    int rem = id - br * (Bn * 33);
    int b = rem / 33, j = rem - b * 33;
    int tid = threadIdx.x;

    const float* src;
    const float* uvec;
    if (j < NN) {
        src = (br ? msg2 : msg1) + (long long)(b * NN + j) * RL * H;
        uvec = g_u + H;
    } else {
        src = xs + ((long long)b * S + (br ? 20 : 1)) * H;
        uvec = g_u;
    }
    const float4* s4 = (const float4*)src;
    float p = 0.f;
#pragma unroll
    for (int it = 0; it < RL * H / 4 / 128; it++) {
        int i = it * 128 + tid;
        float4 v = s4[i];
        const float* up = uvec + (i % (H / 4)) * 4;
        p += v.x * up[0] + v.y * up[1] + v.z * up[2] + v.w * up[3];
    }
#pragma unroll
    for (int o = 16; o > 0; o >>= 1) p += __shfl_xor_sync(0xffffffffu, p, o);
    if ((tid & 31) == 0) wred[tid >> 5] = p;
    __syncthreads();
    if (tid == 0) {
        float tot = (wred[0] + wred[1] + wred[2] + wred[3]) * (1.f / RL);
        if (j < NN) g_md[(br * Bn + b) * NN + j] = tot;
        else        g_feas[br * Bn + b] = tot;
    }
}

__global__ void rsoftmax_kernel(const float* __restrict__ dist1,
                                const float* __restrict__ dist2,
                                const float* __restrict__ wb,
                                const float* __restrict__ bb)
{
    int br = blockIdx.x >> 5, b = blockIdx.x & 31;
    int lane = threadIdx.x;
    float pre = g_feas[br * Bn + b] + g_md[(br * Bn + b) * NN + lane] + g_u[2 * H];
    float z = pre >= 0.f ? pre : NEG * pre;
    const float* dist = br ? dist2 : dist1;
    float v = z + dist[b * NN + lane] * wb[0] + bb[0];
    float m = v;
#pragma unroll
    for (int o = 16; o > 0; o >>= 1) m = fmaxf(m, __shfl_xor_sync(0xffffffffu, m, o));
    float e = __expf(v - m), s = e;
#pragma unroll
    for (int o = 16; o > 0; o >>= 1) s += __shfl_xor_sync(0xffffffffu, s, o);
    (br ? g_att2 : g_att1)[b * NN + lane] = e / s;
}

// ---------------- x = xs (+ gated messages) -> bf16 pairs --------------------
__global__ void build_x_kernel(const float* __restrict__ xs)
{
    int idx = blockIdx.x * 256 + threadIdx.x;
    float4 v = ((const float4*)xs)[idx];
    int h4 = idx % (H / 4);
    int s = (idx / (H / 4)) % S;
    int b = idx / (S * H / 4);
    if (s >= 1 && s < 9) {
        int l = s - 1;
        const float4* m4 = (const float4*)g_msg1;
#pragma unroll 4
        for (int n = 0; n < NN; n++) {
            float a = g_att1[b * NN + n];
            float4 m = m4[((b * NN + n) * RL + l) * (H / 4) + h4];
            v.x += a * m.x; v.y += a * m.y; v.z += a * m.z; v.w += a * m.w;
        }
    } else if (s >= 20 && s < 28) {
        int l = s - 20;
        const float4* m4 = (const float4*)g_msg2;
#pragma unroll 4
        for (int n = 0; n < NN; n++) {
            float a = g_att2[b * NN + n];
            float4 m = m4[((b * NN + n) * RL + l) * (H / 4) + h4];
            v.x += a * m.x; v.y += a * m.y; v.z += a * m.z; v.w += a * m.w;
        }
    }
    uint2 hv, lv; split4(v, hv, lv);
    ((uint2*)g_xh)[idx] = hv;
    ((uint2*)g_xl)[idx] = lv;
}

// ---------------- row softmax (warp/row) -> bf16 pairs -----------------------
__global__ __launch_bounds__(256) void softmax_rows_kernel()
{
    int warp = threadIdx.x >> 5, lane = threadIdx.x & 31;
    long long row = (long long)blockIdx.x * 8 + warp;
    const float4* r4 = (const float4*)(g_probs + row * S);
    float4 x[4];
    float m = -3.4e38f;
#pragma unroll
    for (int k = 0; k < 4; k++) {
        x[k] = r4[lane + 32 * k];
        m = fmaxf(m, fmaxf(fmaxf(x[k].x, x[k].y), fmaxf(x[k].z, x[k].w)));
    }
#pragma unroll
    for (int o = 16; o > 0; o >>= 1) m = fmaxf(m, __shfl_xor_sync(0xffffffffu, m, o));
    float s = 0.f;
#pragma unroll
    for (int k = 0; k < 4; k++) {
        x[k].x = __expf(x[k].x - m); x[k].y = __expf(x[k].y - m);
        x[k].z = __expf(x[k].z - m); x[k].w = __expf(x[k].w - m);
        s += x[k].x + x[k].y + x[k].z + x[k].w;
    }
#pragma unroll
    for (int o = 16; o > 0; o >>= 1) s += __shfl_xor_sync(0xffffffffu, s, o);
    float inv = 1.f / s;
    uint2* ph4 = (uint2*)(g_ph + row * S);
    uint2* pl4 = (uint2*)(g_pl + row * S);
#pragma unroll
    for (int k = 0; k < 4; k++) {
        x[k].x *= inv; x[k].y *= inv; x[k].z *= inv; x[k].w *= inv;
        uint2 hv, lv; split4(x[k], hv, lv);
        ph4[lane + 32 * k] = hv;
        pl4[lane + 32 * k] = lv;
    }
}

// ---------------- launch ----------------
extern "C" void kernel_launch(void* const* d_in, const int* in_sizes, int n_in,
                              void* d_out, int out_size)
{
    const float* xs    = (const float*)d_in[0];
    const float* n1emb = (const float*)d_in[1];
    const float* n2emb = (const float*)d_in[2];
    const float* dist1 = (const float*)d_in[3];
    const float* dist2 = (const float*)d_in[4];
    const float* Wq    = (const float*)d_in[5];
    const float* bq    = (const float*)d_in[6];
    const float* Wk    = (const float*)d_in[7];
    const float* bk    = (const float*)d_in[8];
    const float* Wv    = (const float*)d_in[9];
    const float* bv    = (const float*)d_in[10];
    const float* Wa    = (const float*)d_in[11];
    const float* ba    = (const float*)d_in[12];
    const float* Wattn = (const float*)d_in[13];
    const float* battn = (const float*)d_in[14];
    const float* wb    = (const float*)d_in[15];
    const float* bb    = (const float*)d_in[16];
    float* out = (float*)d_out;

    float *pp, *pm1, *pm2, *pqeP, *pzP, *pbias;
    __nv_bfloat16 *pwh, *pwl, *pwknh, *pwknl, *pqeh, *pqel, *pxh, *pxl,
                  *pqkh, *pqkl, *pvh, *pvl, *pph, *ppl, *pah, *pal;
    cudaGetSymbolAddress((void**)&pp,    g_probs);
    cudaGetSymbolAddress((void**)&pm1,   g_msg1);
    cudaGetSymbolAddress((void**)&pm2,   g_msg2);
    cudaGetSymbolAddress((void**)&pqeP,  g_qeP);
    cudaGetSymbolAddress((void**)&pzP,   g_zP);
    cudaGetSymbolAddress((void**)&pbias, g_bias);
    cudaGetSymbolAddress((void**)&pwh,   g_Wh);
    cudaGetSymbolAddress((void**)&pwl,   g_Wl);
    cudaGetSymbolAddress((void**)&pwknh, g_WkNh);
    cudaGetSymbolAddress((void**)&pwknl, g_WkNl);
    cudaGetSymbolAddress((void**)&pqeh,  g_qeh);
    cudaGetSymbolAddress((void**)&pqel,  g_qel);
    cudaGetSymbolAddress((void**)&pxh,   g_xh);
    cudaGetSymbolAddress((void**)&pxl,   g_xl);
    cudaGetSymbolAddress((void**)&pqkh,  g_qkh);
    cudaGetSymbolAddress((void**)&pqkl,  g_qkl);
    cudaGetSymbolAddress((void**)&pvh,   g_vTh);
    cudaGetSymbolAddress((void**)&pvl,   g_vTl);
    cudaGetSymbolAddress((void**)&pph,   g_ph);
    cudaGetSymbolAddress((void**)&ppl,   g_pl);
    cudaGetSymbolAddress((void**)&pah,   g_qAh);
    cudaGetSymbolAddress((void**)&pal,   g_qAl);

    cudaFuncSetAttribute(bgemm<0, false>, cudaFuncAttributeMaxDynamicSharedMemorySize, BG_SMEM);
    cudaFuncSetAttribute(bgemm<0, true>,  cudaFuncAttributeMaxDynamicSharedMemorySize, BG_SMEM);
    cudaFuncSetAttribute(bgemm<3, false>, cudaFuncAttributeMaxDynamicSharedMemorySize, BG_SMEM);

    // prep
    tsplit_all<<<(1280 * H + H * NE + 1280 + 255) / 256, 256>>>(Wq, Wk, Wv, bq, bk, bv);
    u_kernel<<<49, 256>>>(Wa, Wattn, ba, battn);
    sgat_kernel<<<512 * (H / 4) / 256, 256>>>(xs);

    // qe slabs: split-K 6 x 128 over K=768  (grid 2x4x6 = 48 CTAs)
    bgemm<0, true><<<dim3(2, 4, 6), 256, BG_SMEM>>>(
        pah, pal, pwh, pwl, nullptr, pqeP, nullptr, nullptr, nullptr, nullptr,
        H, H, NE, 128, 1.f, 0, 0, (long long)512 * NE);
    qe_finish<<<128, 256>>>();

    // z slabs: split-K 2 x 128 over K=256 (grid 6x4x2 = 48 CTAs)
    bgemm<0, true><<<dim3(6, 4, 2), 256, BG_SMEM>>>(
        pqeh, pqel, pwknh, pwknl, nullptr, pzP, nullptr, nullptr, nullptr, nullptr,
        NE, NE, H, 128, 1.f, 0, 0, (long long)512 * H);
    z_finish<<<384, 256>>>();
    c_kernel<<<64, 256>>>();

    // neighbor attention via emb·z + messages (both branches)
    neigh_kernel<<<2 * Bn * NN, 256>>>(n1emb, n2emb);

    // gate attention + x pairs
    rscore_kernel<<<2 * Bn * 33, 128>>>(xs, pm1, pm2);
    rsoftmax_kernel<<<2 * Bn, 32>>>(dist1, dist2, wb, bb);
    build_x_kernel<<<(Bn * S * H / 4) / 256, 256>>>(xs);

    // fused q/k/v projections: M = 16384 -> 128 M-tiles, N = 1280 -> 10 N-tiles
    bgemm<3, false><<<dim3(10, 128, 1), 256, BG_SMEM>>>(
        pxh, pxl, pwh, pwl, pbias, nullptr, pqkh, pqkl, pvh, pvl,
        H, H, 512, H, 1.f, 0, 0, 0);

    // scores = SCALE * q @ k^T (batched, grid 4x4x32 = 512)
    bgemm<0, false><<<dim3(4, 4, 32), 256, BG_SMEM>>>(
        pqkh, pqkl, pqkh + 256, pqkl + 256, nullptr, pp,
        nullptr, nullptr, nullptr, nullptr,
        512, 512, S, NE, SCALE,
        (long long)S * 512, (long long)S * 512, (long long)S * S);

    softmax_rows_kernel<<<Bn * S / 8, 256>>>();

    // out = probs @ v (batched, grid 6x4x32 = 768)
    bgemm<0, false><<<dim3(6, 4, 32), 256, BG_SMEM>>>(
        pph, ppl, pvh, pvl, nullptr, out, nullptr, nullptr, nullptr, nullptr,
        512, 512, H, S, 1.f,
        (long long)S * S, (long long)H * S, (long long)S * H);
}

// round 16
// speedup vs baseline: 1.0974x; 1.0335x over previous
#include <cuda_runtime.h>
#include <cuda_bf16.h>
#include <cstdint>

// ---------------- problem constants ----------------
namespace {
constexpr int Bn = 32;
constexpr int S  = 512;
constexpr int H  = 768;
constexpr int NN = 32;
constexpr int T  = 32;
constexpr int NE = 256;
constexpr int AE = 128;
constexpr int RL = 8;
constexpr float SCALE = 0.0625f;
constexpr float NEG   = 0.01f;
}

// ---------------- scratch ----------------
__device__ float g_probs[Bn * S * S];
__device__ float g_msg1 [Bn * NN * RL * H];
__device__ float g_msg2 [Bn * NN * RL * H];
__device__ float g_qe   [2 * Bn * RL * NE];
__device__ float g_qeP  [6 * 512 * NE];         // split-K partial slabs
__device__ float g_z    [2 * Bn * RL * H];
__device__ float g_zP   [2 * 512 * H];
__device__ float g_c    [2 * Bn * RL];
__device__ float g_att1 [Bn * NN];
__device__ float g_att2 [Bn * NN];
__device__ float g_u    [2 * H + 1];
__device__ float g_md   [2 * Bn * NN];
__device__ float g_feas [2 * Bn];
__device__ float g_bias [1280];

__device__ __nv_bfloat16 g_Wh  [1280 * H], g_Wl  [1280 * H];  // stacked WqT|WkT|WvT
__device__ __nv_bfloat16 g_WkNh[H * NE],   g_WkNl[H * NE];    // Wk original layout
__device__ __nv_bfloat16 g_qeh [512 * NE], g_qel [512 * NE];
__device__ __nv_bfloat16 g_xh  [Bn * S * H], g_xl [Bn * S * H];
__device__ __nv_bfloat16 g_qkh [Bn * S * 512], g_qkl[Bn * S * 512];
__device__ __nv_bfloat16 g_vTh [Bn * H * S], g_vTl[Bn * H * S];
__device__ __nv_bfloat16 g_ph  [Bn * S * S], g_pl [Bn * S * S];
__device__ __nv_bfloat16 g_qAh [512 * H],   g_qAl [512 * H];

// ---------------- helpers ----------------
__device__ __forceinline__ uint32_t smem_u32(const void* p) {
    uint32_t a;
    asm("{ .reg .u64 t; cvta.to.shared.u64 t, %1; cvt.u32.u64 %0, t; }" : "=r"(a) : "l"(p));
    return a;
}
__device__ __forceinline__ uint32_t bpack(__nv_bfloat16 a, __nv_bfloat16 b) {
    __nv_bfloat162 t = __halves2bfloat162(a, b);
    return *reinterpret_cast<uint32_t*>(&t);
}
__device__ __forceinline__ uint32_t fpack(float a, float b) {
    __nv_bfloat162 t = __floats2bfloat162_rn(a, b);
    return *reinterpret_cast<uint32_t*>(&t);
}
__device__ __forceinline__ void split4(float4 v, uint2& hv, uint2& lv) {
    __nv_bfloat16 h0 = __float2bfloat16(v.x), h1 = __float2bfloat16(v.y);
    __nv_bfloat16 h2 = __float2bfloat16(v.z), h3 = __float2bfloat16(v.w);
    hv.x = bpack(h0, h1); hv.y = bpack(h2, h3);
    lv.x = fpack(v.x - __bfloat162float(h0), v.y - __bfloat162float(h1));
    lv.y = fpack(v.z - __bfloat162float(h2), v.w - __bfloat162float(h3));
}
__device__ __forceinline__ void ldsm4(uint32_t& r0, uint32_t& r1, uint32_t& r2,
                                      uint32_t& r3, uint32_t a) {
    asm volatile("ldmatrix.sync.aligned.m8n8.x4.shared.b16 {%0,%1,%2,%3}, [%4];"
                 : "=r"(r0), "=r"(r1), "=r"(r2), "=r"(r3) : "r"(a));
}
__device__ __forceinline__ void mma16816(float* d, const uint32_t* a, const uint32_t* b) {
    asm volatile(
        "mma.sync.aligned.m16n8k16.row.col.f32.bf16.bf16.f32 "
        "{%0,%1,%2,%3}, {%4,%5,%6,%7}, {%8,%9}, {%0,%1,%2,%3};"
        : "+f"(d[0]), "+f"(d[1]), "+f"(d[2]), "+f"(d[3])
        : "r"(a[0]), "r"(a[1]), "r"(a[2]), "r"(a[3]), "r"(b[0]), "r"(b[1]));
}

// ================= all-bf16 cp.async bf16x3 GEMM, CTA 128x128 =================
// 8 warps (2x4), warp tile 64x32, BK=64, SINGLE-stage buffer, 2 CTAs/SM.
// Co-residency is the pipeline: while one CTA waits on cp.async, the peer
// CTA's warps issue MMAs (self-stabilizing alternation).
// ROWB=144: row stride 9 octets (odd) -> ldmatrix conflict-free.
// EPI 0: fp32 out.  EPI 3: qkv routing (qk pairs / v SMEM-transposed pairs).
// SK: blockIdx.z = K-slice (length K); output slab at Cf + bz*sC.
constexpr int ROWB  = 144;
constexpr int MTILE = 128 * ROWB;     // 18432
constexpr int STG   = 4 * MTILE;      // 73728
constexpr int BG_SMEM = STG;          // single stage -> 2 CTAs/SM (147 KB)

template<int EPI, bool SK>
__global__ __launch_bounds__(256, 2) void bgemm(
    const __nv_bfloat16* __restrict__ Ahp, const __nv_bfloat16* __restrict__ Alp,
    const __nv_bfloat16* __restrict__ Bhp, const __nv_bfloat16* __restrict__ Blp,
    const float* __restrict__ bias, float* __restrict__ Cf,
    __nv_bfloat16* __restrict__ Ch, __nv_bfloat16* __restrict__ Cl,
    __nv_bfloat16* __restrict__ Dh, __nv_bfloat16* __restrict__ Dl,
    int lda, int ldb, int ldc, int K, float alpha,
    long long sA, long long sB, long long sC)
{
    extern __shared__ char smem[];
    const uint32_t sb = smem_u32(smem);
    const int tid = threadIdx.x, w = tid >> 5, lane = tid & 31;
    const int m0 = blockIdx.y * 128, n0 = blockIdx.x * 128, bz = blockIdx.z;
    int koff = 0;
    if (SK) {
        koff = bz * K;
        Cf += bz * sC;
    } else {
        Ahp += bz * sA; Alp += bz * sA;
        Bhp += bz * sB; Blp += bz * sB;
        if (EPI == 0) Cf += bz * sC;
    }

    const int wm = (w >> 2) * 64, wn = (w & 3) * 32;
    float acc[4][4][4];
#pragma unroll
    for (int a = 0; a < 4; a++)
#pragma unroll
        for (int b = 0; b < 4; b++)
#pragma unroll
            for (int c = 0; c < 4; c++) acc[a][b][c] = 0.f;

    const int nch = K >> 6;   // BK = 64

    auto issue = [&](int c) {
        const int k0 = (c << 6) + koff;
#pragma unroll
        for (int mat = 0; mat < 4; mat++) {
            const __nv_bfloat16* g = (mat == 0) ? Ahp : (mat == 1) ? Alp
                                   : (mat == 2) ? Bhp : Blp;
            const int rb = (mat < 2) ? m0 : n0;
            const int ld = (mat < 2) ? lda : ldb;
#pragma unroll
            for (int it = 0; it < 4; ++it) {
                int i = (it << 8) + tid, row = i >> 3, c8 = i & 7;
                const __nv_bfloat16* src = g + (long long)(rb + row) * ld + k0 + (c8 << 3);
                asm volatile("cp.async.cg.shared.global [%0], [%1], 16;"
                             :: "r"(sb + mat * MTILE + row * ROWB + (c8 << 4)), "l"(src));
            }
        }
        asm volatile("cp.async.commit_group;");
    };

    const int q = lane >> 3, r = lane & 7;
    const int aRow = ((q & 1) << 3) + r;
    const int aCol = (q >> 1) << 4;
    const int bRow = ((q >> 1) << 3) + r;
    const int bCol = (q & 1) << 4;

    auto compute = [&]() {
        const uint32_t Ah = sb;
        const uint32_t Al = Ah + MTILE, Bh = Ah + 2 * MTILE, Bl = Ah + 3 * MTILE;
#pragma unroll
        for (int s = 0; s < 4; s++) {
            const int kOff = s * 32;
            uint32_t bh[4][2], bl[4][2];
#pragma unroll
            for (int np = 0; np < 2; np++) {
                uint32_t off = (uint32_t)(wn + np * 16 + bRow) * ROWB + kOff + bCol;
                ldsm4(bh[2 * np][0], bh[2 * np][1],
                      bh[2 * np + 1][0], bh[2 * np + 1][1], Bh + off);
                ldsm4(bl[2 * np][0], bl[2 * np][1],
                      bl[2 * np + 1][0], bl[2 * np + 1][1], Bl + off);
            }
#pragma unroll
            for (int mt = 0; mt < 4; mt++) {
                uint32_t ah[4], al[4];
                uint32_t off = (uint32_t)(wm + mt * 16 + aRow) * ROWB + kOff + aCol;
                ldsm4(ah[0], ah[1], ah[2], ah[3], Ah + off);
                ldsm4(al[0], al[1], al[2], al[3], Al + off);
#pragma unroll
                for (int nt = 0; nt < 4; nt++) {
                    mma16816(acc[mt][nt], ah, bh[nt]);
                    mma16816(acc[mt][nt], ah, bl[nt]);
                    mma16816(acc[mt][nt], al, bh[nt]);
                }
            }
        }
    };

    for (int c = 0; c < nch; c++) {
        issue(c);
        asm volatile("cp.async.wait_group 0;");
        __syncthreads();
        compute();
        __syncthreads();
    }

    const int gid = lane >> 2, tig = lane & 3;

    if (EPI == 3 && n0 >= 512) {
        // v tile: transpose through SMEM (67.6 KB fits the 72 KB buffer),
        // then coalesced bf16 pair stores.
        float* st = (float*)smem;   // [n][m], stride 132
#pragma unroll
        for (int mt = 0; mt < 4; mt++)
#pragma unroll
            for (int half = 0; half < 2; half++) {
                const int m = wm + mt * 16 + gid + half * 8;
#pragma unroll
                for (int nt = 0; nt < 4; nt++) {
                    const int n = wn + nt * 8 + tig * 2;
                    st[n * 132 + m]       = acc[mt][nt][half * 2 + 0] + bias[n0 + n];
                    st[(n + 1) * 132 + m] = acc[mt][nt][half * 2 + 1] + bias[n0 + n + 1];
                }
            }
        __syncthreads();
        const long long bb2 = m0 >> 9;
        const int t0 = m0 & 511, nvb = n0 - 512;
#pragma unroll
        for (int it = 0; it < 32; it++) {
            int i = it * 256 + tid;
            int n = i >> 6, mc = (i & 63) << 1;
            float v0 = st[n * 132 + mc], v1 = st[n * 132 + mc + 1];
            __nv_bfloat16 h0 = __float2bfloat16(v0), h1 = __float2bfloat16(v1);
            long long gi = (bb2 * 768 + nvb + n) * 512 + t0 + mc;
            *(uint32_t*)&Dh[gi] = bpack(h0, h1);
            *(uint32_t*)&Dl[gi] =
                fpack(v0 - __bfloat162float(h0), v1 - __bfloat162float(h1));
        }
    } else {
#pragma unroll
        for (int mt = 0; mt < 4; mt++)
#pragma unroll
            for (int half = 0; half < 2; half++) {
                const long long m = m0 + wm + mt * 16 + gid + half * 8;
#pragma unroll
                for (int nt = 0; nt < 4; nt++) {
                    float v0 = acc[mt][nt][half * 2 + 0];
                    float v1 = acc[mt][nt][half * 2 + 1];
                    const int n = n0 + wn + nt * 8 + tig * 2;
                    if (EPI == 0) {
                        v0 *= alpha; v1 *= alpha;
                        if (bias) { v0 += bias[n]; v1 += bias[n + 1]; }
                        *(float2*)&Cf[m * ldc + n] = make_float2(v0, v1);
                    } else {  // EPI == 3, qk half
                        v0 += bias[n]; v1 += bias[n + 1];
                        __nv_bfloat16 h0 = __float2bfloat16(v0), h1 = __float2bfloat16(v1);
                        *(uint32_t*)&Ch[m * 512 + n] = bpack(h0, h1);
                        *(uint32_t*)&Cl[m * 512 + n] =
                            fpack(v0 - __bfloat162float(h0), v1 - __bfloat162float(h1));
                    }
                }
            }
    }
}

// ---------------- split-K finish: qe = sum(slabs) + bq; emit fp32 + pairs ----
__global__ void qe_finish()
{
    int idx = blockIdx.x * 256 + threadIdx.x;   // 32768 float4s
    int n4 = (idx % (NE / 4)) * 4;
    float4 s = ((const float4*)g_qeP)[idx];
#pragma unroll
    for (int k = 1; k < 6; k++) {
        float4 p = ((const float4*)g_qeP)[k * (512 * NE / 4) + idx];
        s.x += p.x; s.y += p.y; s.z += p.z; s.w += p.w;
    }
    s.x += g_bias[n4]; s.y += g_bias[n4 + 1];
    s.z += g_bias[n4 + 2]; s.w += g_bias[n4 + 3];
    ((float4*)g_qe)[idx] = s;
    uint2 hv, lv; split4(s, hv, lv);
    ((uint2*)g_qeh)[idx] = hv;
    ((uint2*)g_qel)[idx] = lv;
}

// ---------------- split-K finish: z = slab0 + slab1 --------------------------
__global__ void z_finish()
{
    int idx = blockIdx.x * 256 + threadIdx.x;   // 98304 float4s
    float4 a = ((const float4*)g_zP)[idx];
    float4 b = ((const float4*)g_zP)[512 * H / 4 + idx];
    a.x += b.x; a.y += b.y; a.z += b.z; a.w += b.w;
    ((float4*)g_z)[idx] = a;
}

// ---------------- weights: stacked WT pairs + WkN pairs + bias ---------------
__global__ void tsplit_all(const float* __restrict__ Wq, const float* __restrict__ Wk,
                           const float* __restrict__ Wv, const float* __restrict__ bq,
                           const float* __restrict__ bk, const float* __restrict__ bv)
{
    int idx = blockIdx.x * 256 + threadIdx.x;
    if (idx < 1280 * H) {
        const float* W; int Nn, nbase, local;
        if (idx < NE * H)            { W = Wq; Nn = NE; nbase = 0;   local = idx; }
        else if (idx < 2 * NE * H)   { W = Wk; Nn = NE; nbase = 256; local = idx - NE * H; }
        else                         { W = Wv; Nn = H;  nbase = 512; local = idx - 2 * NE * H; }
        int k = local / Nn, n = local - k * Nn;
        float x = W[local];                       // coalesced read
        __nv_bfloat16 h = __float2bfloat16(x);
        int oi = (nbase + n) * H + k;             // transposed scatter store
        g_Wh[oi] = h;
        g_Wl[oi] = __float2bfloat16(x - __bfloat162float(h));
    } else if (idx < 1280 * H + H * NE) {
        int local = idx - 1280 * H;
        float x = Wk[local];
        __nv_bfloat16 h = __float2bfloat16(x);
        g_WkNh[local] = h;
        g_WkNl[local] = __float2bfloat16(x - __bfloat162float(h));
    } else if (idx < 1280 * H + H * NE + 1280) {
        int j = idx - 1280 * H - H * NE;
        g_bias[j] = (j < 256) ? bq[j] : (j < 512) ? bk[j - 256] : bv[j - 512];
    }
}

// ---------------- gather + split region rows for qe GEMM ---------------------
__global__ void sgat_kernel(const float* __restrict__ xs)
{
    int idx = blockIdx.x * 256 + threadIdx.x;
    int m = idx / (H / 4), r4 = idx - m * (H / 4);
    int br = m >> 8, b = (m >> 3) & 31, l = m & 7;
    float4 v = ((const float4*)(xs + ((long long)b * S + (br ? 20 : 1) + l) * H))[r4];
    uint2 hv, lv; split4(v, hv, lv);
    ((uint2*)g_qAh)[idx] = hv;
    ((uint2*)g_qAl)[idx] = lv;
}

// ---------------- c[row] = qe[row]·bk ----------------------------------------
__global__ void c_kernel()
{
    int row = blockIdx.x * 8 + (threadIdx.x >> 5);
    int lane = threadIdx.x & 31;
    float p = 0.f;
#pragma unroll
    for (int i = 0; i < 8; i++) {
        int e = lane + i * 32;
        p += g_qe[row * NE + e] * g_bias[256 + e];
    }
#pragma unroll
    for (int o = 16; o > 0; o >>= 1) p += __shfl_xor_sync(0xffffffffu, p, o);
    if (lane == 0) g_c[row] = p;
}

// ---------------- u = Wa @ Wattn halves; cbase -------------------------------
__global__ void u_kernel(const float* __restrict__ Wa, const float* __restrict__ Wattn,
                         const float* __restrict__ ba, const float* __restrict__ battn)
{
    if (blockIdx.x < 48) {
        int gt = blockIdx.x * 256 + threadIdx.x;
        int g = gt >> 3, sub = gt & 7;
        int j = g / H, h = g - j * H;
        float acc = 0.f;
#pragma unroll 4
        for (int a = sub; a < AE; a += 8) acc += Wa[h * AE + a] * Wattn[j * AE + a];
        acc += __shfl_down_sync(0xffffffffu, acc, 4, 8);
        acc += __shfl_down_sync(0xffffffffu, acc, 2, 8);
        acc += __shfl_down_sync(0xffffffffu, acc, 1, 8);
        if (sub == 0) g_u[g] = acc;
    } else {
        __shared__ float red[256];
        int tid = threadIdx.x;
        float v = 0.f;
        if (tid < AE) v = ba[tid] * (Wattn[tid] + Wattn[AE + tid]);
        red[tid] = v; __syncthreads();
        for (int s2 = 128; s2 > 0; s2 >>= 1) {
            if (tid < s2) red[tid] += red[tid + s2];
            __syncthreads();
        }
        if (tid == 0) g_u[2 * H] = red[0] + battn[0];
    }
}

// ---------------- per-(br,b,n): scores from z -> softmax -> message ----------
__global__ __launch_bounds__(256) void neigh_kernel(
    const float* __restrict__ e1, const float* __restrict__ e2)
{
    __shared__ float zs[RL * H];        // 24 KB
    __shared__ float es[T * 196];       // 24.5 KB
    __shared__ float awT[T * 8];        // [t][l]
    __shared__ float cs[RL];
    float* red = es;                    // 8 x 256 reduction buffer (aliases es)

    int br = blockIdx.x >> 10;
    int b = (blockIdx.x >> 5) & 31, n = blockIdx.x & 31;
    int tid = threadIdx.x;
    const float* emb = (br ? e2 : e1) + (long long)(b * NN + n) * T * H;
    const float4* eb4 = (const float4*)emb;

    const float4* z4 = (const float4*)(g_z + (long long)(br * 256 + b * 8) * H);
#pragma unroll
    for (int it = 0; it < 6; it++) {
        int i = it * 256 + tid;
        *(float4*)&zs[i * 4] = z4[i];
    }
    if (tid < 8) cs[tid] = g_c[br * 256 + b * 8 + tid];
    __syncthreads();

    const int tt = tid & 31, sh = tid >> 5;
    float acc8[8];
#pragma unroll
    for (int l = 0; l < 8; l++) acc8[l] = 0.f;

#pragma unroll
    for (int ch = 0; ch < 4; ch++) {
        for (int i = tid; i < T * 48; i += 256) {
            int t2 = i / 48, h4 = i - t2 * 48;
            *(float4*)&es[t2 * 196 + h4 * 4] = eb4[t2 * (H / 4) + ch * 48 + h4];
        }
        __syncthreads();
        const float4* er = (const float4*)&es[tt * 196 + sh * 24];
        float4 ev[6];
#pragma unroll
        for (int j = 0; j < 6; j++) ev[j] = er[j];
#pragma unroll
        for (int l = 0; l < 8; l++) {
            const float4* zr = (const float4*)&zs[l * H + ch * 192 + sh * 24];
            float a = 0.f;
#pragma unroll
            for (int j = 0; j < 6; j++) {
                float4 zv = zr[j];
                a += ev[j].x * zv.x + ev[j].y * zv.y + ev[j].z * zv.z + ev[j].w * zv.w;
            }
            acc8[l] += a;
        }
        __syncthreads();
    }

#pragma unroll
    for (int l = 0; l < 8; l++) red[sh * 256 + l * 32 + tt] = acc8[l];
    __syncthreads();

    const int l = tid >> 5;
    float s = 0.f;
#pragma unroll
    for (int k = 0; k < 8; k++) s += red[k * 256 + tid];
    s = (s + cs[l]) * SCALE;
    float m = s;
#pragma unroll
    for (int o = 16; o > 0; o >>= 1) m = fmaxf(m, __shfl_xor_sync(0xffffffffu, m, o));
    float ex = __expf(s - m), sum = ex;
#pragma unroll
    for (int o = 16; o > 0; o >>= 1) sum += __shfl_xor_sync(0xffffffffu, sum, o);
    awT[tt * 8 + l] = ex / sum;
    __syncthreads();

    if (tid < H / 4) {
        const int h4 = tid;
        float4 mac[8];
#pragma unroll
        for (int l2 = 0; l2 < 8; l2++) mac[l2] = make_float4(0.f, 0.f, 0.f, 0.f);
        for (int t2 = 0; t2 < T; t2++) {
            float4 e = eb4[t2 * (H / 4) + h4];
            float4 w0 = *(const float4*)&awT[t2 * 8];
            float4 w1 = *(const float4*)&awT[t2 * 8 + 4];
            float wv[8] = {w0.x, w0.y, w0.z, w0.w, w1.x, w1.y, w1.z, w1.w};
#pragma unroll
            for (int l2 = 0; l2 < 8; l2++) {
                mac[l2].x += wv[l2] * e.x; mac[l2].y += wv[l2] * e.y;
                mac[l2].z += wv[l2] * e.z; mac[l2].w += wv[l2] * e.w;
            }
        }
        float4* mb4 = (float4*)((br ? g_msg2 : g_msg1) + (long long)(b * NN + n) * RL * H);
#pragma unroll
        for (int l2 = 0; l2 < 8; l2++) mb4[l2 * (H / 4) + h4] = mac[l2];
    }
}

// ---------------- region gate dots -------------------------------------------
__global__ __launch_bounds__(128) void rscore_kernel(
    const float* __restrict__ xs, const float* __restrict__ msg1,
    const float* __restrict__ msg2)
{
    __shared__ float wred[4];
    int id = blockIdx.x;
    int br = id / (Bn * 33);
    int rem = id - br * (Bn * 33);
    int b = rem / 33, j = rem - b * 33;
    int tid = threadIdx.x;

    const float* src;
    const float* uvec;
    if (j < NN) {
        src = (br ? msg2 : msg1) + (long long)(b * NN + j) * RL * H;
        uvec = g_u + H;
    } else {
        src = xs + ((long long)b * S + (br ? 20 : 1)) * H;
        uvec = g_u;
    }
    const float4* s4 = (const float4*)src;
    float p = 0.f;
#pragma unroll
    for (int it = 0; it < RL * H / 4 / 128; it++) {
        int i = it * 128 + tid;
        float4 v = s4[i];
        const float* up = uvec + (i % (H / 4)) * 4;
        p += v.x * up[0] + v.y * up[1] + v.z * up[2] + v.w * up[3];
    }
#pragma unroll
    for (int o = 16; o > 0; o >>= 1) p += __shfl_xor_sync(0xffffffffu, p, o);
    if ((tid & 31) == 0) wred[tid >> 5] = p;
    __syncthreads();
    if (tid == 0) {
        float tot = (wred[0] + wred[1] + wred[2] + wred[3]) * (1.f / RL);
        if (j < NN) g_md[(br * Bn + b) * NN + j] = tot;
        else        g_feas[br * Bn + b] = tot;
    }
}

__global__ void rsoftmax_kernel(const float* __restrict__ dist1,
                                const float* __restrict__ dist2,
                                const float* __restrict__ wb,
                                const float* __restrict__ bb)
{
    int br = blockIdx.x >> 5, b = blockIdx.x & 31;
    int lane = threadIdx.x;
    float pre = g_feas[br * Bn + b] + g_md[(br * Bn + b) * NN + lane] + g_u[2 * H];
    float z = pre >= 0.f ? pre : NEG * pre;
    const float* dist = br ? dist2 : dist1;
    float v = z + dist[b * NN + lane] * wb[0] + bb[0];
    float m = v;
#pragma unroll
    for (int o = 16; o > 0; o >>= 1) m = fmaxf(m, __shfl_xor_sync(0xffffffffu, m, o));
    float e = __expf(v - m), s = e;
#pragma unroll
    for (int o = 16; o > 0; o >>= 1) s += __shfl_xor_sync(0xffffffffu, s, o);
    (br ? g_att2 : g_att1)[b * NN + lane] = e / s;
}

// ---------------- x = xs (+ gated messages) -> bf16 pairs --------------------
__global__ void build_x_kernel(const float* __restrict__ xs)
{
    int idx = blockIdx.x * 256 + threadIdx.x;
    float4 v = ((const float4*)xs)[idx];
    int h4 = idx % (H / 4);
    int s = (idx / (H / 4)) % S;
    int b = idx / (S * H / 4);
    if (s >= 1 && s < 9) {
        int l = s - 1;
        const float4* m4 = (const float4*)g_msg1;
#pragma unroll 4
        for (int n = 0; n < NN; n++) {
            float a = g_att1[b * NN + n];
            float4 m = m4[((b * NN + n) * RL + l) * (H / 4) + h4];
            v.x += a * m.x; v.y += a * m.y; v.z += a * m.z; v.w += a * m.w;
        }
    } else if (s >= 20 && s < 28) {
        int l = s - 20;
        const float4* m4 = (const float4*)g_msg2;
#pragma unroll 4
        for (int n = 0; n < NN; n++) {
            float a = g_att2[b * NN + n];
            float4 m = m4[((b * NN + n) * RL + l) * (H / 4) + h4];
            v.x += a * m.x; v.y += a * m.y; v.z += a * m.z; v.w += a * m.w;
        }
    }
    uint2 hv, lv; split4(v, hv, lv);
    ((uint2*)g_xh)[idx] = hv;
    ((uint2*)g_xl)[idx] = lv;
}

// ---------------- row softmax (warp/row) -> bf16 pairs -----------------------
__global__ __launch_bounds__(256) void softmax_rows_kernel()
{
    int warp = threadIdx.x >> 5, lane = threadIdx.x & 31;
    long long row = (long long)blockIdx.x * 8 + warp;
    const float4* r4 = (const float4*)(g_probs + row * S);
    float4 x[4];
    float m = -3.4e38f;
#pragma unroll
    for (int k = 0; k < 4; k++) {
        x[k] = r4[lane + 32 * k];
        m = fmaxf(m, fmaxf(fmaxf(x[k].x, x[k].y), fmaxf(x[k].z, x[k].w)));
    }
#pragma unroll
    for (int o = 16; o > 0; o >>= 1) m = fmaxf(m, __shfl_xor_sync(0xffffffffu, m, o));
    float s = 0.f;
#pragma unroll
    for (int k = 0; k < 4; k++) {
        x[k].x = __expf(x[k].x - m); x[k].y = __expf(x[k].y - m);
        x[k].z = __expf(x[k].z - m); x[k].w = __expf(x[k].w - m);
        s += x[k].x + x[k].y + x[k].z + x[k].w;
    }
#pragma unroll
    for (int o = 16; o > 0; o >>= 1) s += __shfl_xor_sync(0xffffffffu, s, o);
    float inv = 1.f / s;
    uint2* ph4 = (uint2*)(g_ph + row * S);
    uint2* pl4 = (uint2*)(g_pl + row * S);
#pragma unroll
    for (int k = 0; k < 4; k++) {
        x[k].x *= inv; x[k].y *= inv; x[k].z *= inv; x[k].w *= inv;
        uint2 hv, lv; split4(x[k], hv, lv);
        ph4[lane + 32 * k] = hv;
        pl4[lane + 32 * k] = lv;
    }
}

// ---------------- launch ----------------
extern "C" void kernel_launch(void* const* d_in, const int* in_sizes, int n_in,
                              void* d_out, int out_size)
{
    const float* xs    = (const float*)d_in[0];
    const float* n1emb = (const float*)d_in[1];
    const float* n2emb = (const float*)d_in[2];
    const float* dist1 = (const float*)d_in[3];
    const float* dist2 = (const float*)d_in[4];
    const float* Wq    = (const float*)d_in[5];
    const float* bq    = (const float*)d_in[6];
    const float* Wk    = (const float*)d_in[7];
    const float* bk    = (const float*)d_in[8];
    const float* Wv    = (const float*)d_in[9];
    const float* bv    = (const float*)d_in[10];
    const float* Wa    = (const float*)d_in[11];
    const float* ba    = (const float*)d_in[12];
    const float* Wattn = (const float*)d_in[13];
    const float* battn = (const float*)d_in[14];
    const float* wb    = (const float*)d_in[15];
    const float* bb    = (const float*)d_in[16];
    float* out = (float*)d_out;

    float *pp, *pm1, *pm2, *pqeP, *pzP, *pbias;
    __nv_bfloat16 *pwh, *pwl, *pwknh, *pwknl, *pqeh, *pqel, *pxh, *pxl,
                  *pqkh, *pqkl, *pvh, *pvl, *pph, *ppl, *pah, *pal;
    cudaGetSymbolAddress((void**)&pp,    g_probs);
    cudaGetSymbolAddress((void**)&pm1,   g_msg1);
    cudaGetSymbolAddress((void**)&pm2,   g_msg2);
    cudaGetSymbolAddress((void**)&pqeP,  g_qeP);
    cudaGetSymbolAddress((void**)&pzP,   g_zP);
    cudaGetSymbolAddress((void**)&pbias, g_bias);
    cudaGetSymbolAddress((void**)&pwh,   g_Wh);
    cudaGetSymbolAddress((void**)&pwl,   g_Wl);
    cudaGetSymbolAddress((void**)&pwknh, g_WkNh);
    cudaGetSymbolAddress((void**)&pwknl, g_WkNl);
    cudaGetSymbolAddress((void**)&pqeh,  g_qeh);
    cudaGetSymbolAddress((void**)&pqel,  g_qel);
    cudaGetSymbolAddress((void**)&pxh,   g_xh);
    cudaGetSymbolAddress((void**)&pxl,   g_xl);
    cudaGetSymbolAddress((void**)&pqkh,  g_qkh);
    cudaGetSymbolAddress((void**)&pqkl,  g_qkl);
    cudaGetSymbolAddress((void**)&pvh,   g_vTh);
    cudaGetSymbolAddress((void**)&pvl,   g_vTl);
    cudaGetSymbolAddress((void**)&pph,   g_ph);
    cudaGetSymbolAddress((void**)&ppl,   g_pl);
    cudaGetSymbolAddress((void**)&pah,   g_qAh);
    cudaGetSymbolAddress((void**)&pal,   g_qAl);

    cudaFuncSetAttribute(bgemm<0, false>, cudaFuncAttributeMaxDynamicSharedMemorySize, BG_SMEM);
    cudaFuncSetAttribute(bgemm<0, true>,  cudaFuncAttributeMaxDynamicSharedMemorySize, BG_SMEM);
    cudaFuncSetAttribute(bgemm<3, false>, cudaFuncAttributeMaxDynamicSharedMemorySize, BG_SMEM);

    // prep
    tsplit_all<<<(1280 * H + H * NE + 1280 + 255) / 256, 256>>>(Wq, Wk, Wv, bq, bk, bv);
    u_kernel<<<49, 256>>>(Wa, Wattn, ba, battn);
    sgat_kernel<<<512 * (H / 4) / 256, 256>>>(xs);

    // qe slabs: split-K 6 x 128 over K=768  (grid 2x4x6 = 48 CTAs)
    bgemm<0, true><<<dim3(2, 4, 6), 256, BG_SMEM>>>(
        pah, pal, pwh, pwl, nullptr, pqeP, nullptr, nullptr, nullptr, nullptr,
        H, H, NE, 128, 1.f, 0, 0, (long long)512 * NE);
    qe_finish<<<128, 256>>>();

    // z slabs: split-K 2 x 128 over K=256 (grid 6x4x2 = 48 CTAs)
    bgemm<0, true><<<dim3(6, 4, 2), 256, BG_SMEM>>>(
        pqeh, pqel, pwknh, pwknl, nullptr, pzP, nullptr, nullptr, nullptr, nullptr,
        NE, NE, H, 128, 1.f, 0, 0, (long long)512 * H);
    z_finish<<<384, 256>>>();
    c_kernel<<<64, 256>>>();

    // neighbor attention via emb·z + messages (both branches)
    neigh_kernel<<<2 * Bn * NN, 256>>>(n1emb, n2emb);

    // gate attention + x pairs
    rscore_kernel<<<2 * Bn * 33, 128>>>(xs, pm1, pm2);
    rsoftmax_kernel<<<2 * Bn, 32>>>(dist1, dist2, wb, bb);
    build_x_kernel<<<(Bn * S * H / 4) / 256, 256>>>(xs);

    // fused q/k/v projections: M = 16384 -> 128 M-tiles, N = 1280 -> 10 N-tiles
    bgemm<3, false><<<dim3(10, 128, 1), 256, BG_SMEM>>>(
        pxh, pxl, pwh, pwl, pbias, nullptr, pqkh, pqkl, pvh, pvl,
        H, H, 512, H, 1.f, 0, 0, 0);

    // scores = SCALE * q @ k^T (batched, grid 4x4x32 = 512)
    bgemm<0, false><<<dim3(4, 4, 32), 256, BG_SMEM>>>(
        pqkh, pqkl, pqkh + 256, pqkl + 256, nullptr, pp,
        nullptr, nullptr, nullptr, nullptr,
        512, 512, S, NE, SCALE,
        (long long)S * 512, (long long)S * 512, (long long)S * S);

    softmax_rows_kernel<<<Bn * S / 8, 256>>>();

    // out = probs @ v (batched, grid 6x4x32 = 768)
    bgemm<0, false><<<dim3(6, 4, 32), 256, BG_SMEM>>>(
        pph, ppl, pvh, pvl, nullptr, out, nullptr, nullptr, nullptr, nullptr,
        512, 512, H, S, 1.f,
        (long long)S * S, (long long)H * S, (long long)S * H);
}

// round 17
// speedup vs baseline: 1.1106x; 1.0121x over previous
#include <cuda_runtime.h>
#include <cuda_bf16.h>
#include <cstdint>

// ---------------- problem constants ----------------
namespace {
constexpr int Bn = 32;
constexpr int S  = 512;
constexpr int H  = 768;
constexpr int NN = 32;
constexpr int T  = 32;
constexpr int NE = 256;
constexpr int AE = 128;
constexpr int RL = 8;
constexpr float SCALE = 0.0625f;
constexpr float NEG   = 0.01f;
}

// ---------------- scratch ----------------
__device__ float g_probs[Bn * S * S];
__device__ float g_msg1 [Bn * NN * RL * H];
__device__ float g_msg2 [Bn * NN * RL * H];
__device__ float g_qe   [2 * Bn * RL * NE];
__device__ float g_qeP  [12 * 512 * NE];        // split-K partial slabs
__device__ float g_z    [2 * Bn * RL * H];
__device__ float g_zP   [4 * 512 * H];
__device__ float g_c    [2 * Bn * RL];
__device__ float g_att1 [Bn * NN];
__device__ float g_att2 [Bn * NN];
__device__ float g_u    [2 * H + 1];
__device__ float g_md   [2 * Bn * NN];
__device__ float g_feas [2 * Bn];
__device__ float g_bias [1280];

__device__ __nv_bfloat16 g_Wh  [1280 * H], g_Wl  [1280 * H];  // stacked WqT|WkT|WvT
__device__ __nv_bfloat16 g_WkNh[H * NE],   g_WkNl[H * NE];    // Wk original layout
__device__ __nv_bfloat16 g_qeh [512 * NE], g_qel [512 * NE];
__device__ __nv_bfloat16 g_xh  [Bn * S * H], g_xl [Bn * S * H];
__device__ __nv_bfloat16 g_qkh [Bn * S * 512], g_qkl[Bn * S * 512];
__device__ __nv_bfloat16 g_vTh [Bn * H * S], g_vTl[Bn * H * S];
__device__ __nv_bfloat16 g_ph  [Bn * S * S], g_pl [Bn * S * S];
__device__ __nv_bfloat16 g_qAh [512 * H],   g_qAl [512 * H];

// ---------------- helpers ----------------
__device__ __forceinline__ uint32_t smem_u32(const void* p) {
    uint32_t a;
    asm("{ .reg .u64 t; cvta.to.shared.u64 t, %1; cvt.u32.u64 %0, t; }" : "=r"(a) : "l"(p));
    return a;
}
__device__ __forceinline__ uint32_t bpack(__nv_bfloat16 a, __nv_bfloat16 b) {
    __nv_bfloat162 t = __halves2bfloat162(a, b);
    return *reinterpret_cast<uint32_t*>(&t);
}
__device__ __forceinline__ uint32_t fpack(float a, float b) {
    __nv_bfloat162 t = __floats2bfloat162_rn(a, b);
    return *reinterpret_cast<uint32_t*>(&t);
}
__device__ __forceinline__ void split4(float4 v, uint2& hv, uint2& lv) {
    __nv_bfloat16 h0 = __float2bfloat16(v.x), h1 = __float2bfloat16(v.y);
    __nv_bfloat16 h2 = __float2bfloat16(v.z), h3 = __float2bfloat16(v.w);
    hv.x = bpack(h0, h1); hv.y = bpack(h2, h3);
    lv.x = fpack(v.x - __bfloat162float(h0), v.y - __bfloat162float(h1));
    lv.y = fpack(v.z - __bfloat162float(h2), v.w - __bfloat162float(h3));
}
__device__ __forceinline__ void ldsm4(uint32_t& r0, uint32_t& r1, uint32_t& r2,
                                      uint32_t& r3, uint32_t a) {
    asm volatile("ldmatrix.sync.aligned.m8n8.x4.shared.b16 {%0,%1,%2,%3}, [%4];"
                 : "=r"(r0), "=r"(r1), "=r"(r2), "=r"(r3) : "r"(a));
}
__device__ __forceinline__ void mma16816(float* d, const uint32_t* a, const uint32_t* b) {
    asm volatile(
        "mma.sync.aligned.m16n8k16.row.col.f32.bf16.bf16.f32 "
        "{%0,%1,%2,%3}, {%4,%5,%6,%7}, {%8,%9}, {%0,%1,%2,%3};"
        : "+f"(d[0]), "+f"(d[1]), "+f"(d[2]), "+f"(d[3])
        : "r"(a[0]), "r"(a[1]), "r"(a[2]), "r"(a[3]), "r"(b[0]), "r"(b[1]));
}

// ================= all-bf16 cp.async bf16x3 GEMM, CTA 128x128 =================
// 8 warps (2x4), warp tile 64x32, BK=64, SINGLE-stage buffer, 2 CTAs/SM.
// Co-residency is the pipeline. ROWB=144 (odd octets -> conflict-free ldmatrix).
// EPI 0: fp32 out.  EPI 3: qkv routing (qk pairs / v SMEM-transposed pairs).
// SK: blockIdx.z = K-slice (length K); output slab at Cf + bz*sC.
constexpr int ROWB  = 144;
constexpr int MTILE = 128 * ROWB;     // 18432
constexpr int STG   = 4 * MTILE;      // 73728
constexpr int BG_SMEM = STG;          // single stage -> 2 CTAs/SM (147 KB)

template<int EPI, bool SK>
__global__ __launch_bounds__(256, 2) void bgemm(
    const __nv_bfloat16* __restrict__ Ahp, const __nv_bfloat16* __restrict__ Alp,
    const __nv_bfloat16* __restrict__ Bhp, const __nv_bfloat16* __restrict__ Blp,
    const float* __restrict__ bias, float* __restrict__ Cf,
    __nv_bfloat16* __restrict__ Ch, __nv_bfloat16* __restrict__ Cl,
    __nv_bfloat16* __restrict__ Dh, __nv_bfloat16* __restrict__ Dl,
    int lda, int ldb, int ldc, int K, float alpha,
    long long sA, long long sB, long long sC)
{
    extern __shared__ char smem[];
    const uint32_t sb = smem_u32(smem);
    const int tid = threadIdx.x, w = tid >> 5, lane = tid & 31;
    const int m0 = blockIdx.y * 128, n0 = blockIdx.x * 128, bz = blockIdx.z;
    int koff = 0;
    if (SK) {
        koff = bz * K;
        Cf += bz * sC;
    } else {
        Ahp += bz * sA; Alp += bz * sA;
        Bhp += bz * sB; Blp += bz * sB;
        if (EPI == 0) Cf += bz * sC;
    }

    const int wm = (w >> 2) * 64, wn = (w & 3) * 32;
    float acc[4][4][4];
#pragma unroll
    for (int a = 0; a < 4; a++)
#pragma unroll
        for (int b = 0; b < 4; b++)
#pragma unroll
            for (int c = 0; c < 4; c++) acc[a][b][c] = 0.f;

    const int nch = K >> 6;   // BK = 64

    auto issue = [&](int c) {
        const int k0 = (c << 6) + koff;
#pragma unroll
        for (int mat = 0; mat < 4; mat++) {
            const __nv_bfloat16* g = (mat == 0) ? Ahp : (mat == 1) ? Alp
                                   : (mat == 2) ? Bhp : Blp;
            const int rb = (mat < 2) ? m0 : n0;
            const int ld = (mat < 2) ? lda : ldb;
#pragma unroll
            for (int it = 0; it < 4; ++it) {
                int i = (it << 8) + tid, row = i >> 3, c8 = i & 7;
                const __nv_bfloat16* src = g + (long long)(rb + row) * ld + k0 + (c8 << 3);
                asm volatile("cp.async.cg.shared.global [%0], [%1], 16;"
                             :: "r"(sb + mat * MTILE + row * ROWB + (c8 << 4)), "l"(src));
            }
        }
        asm volatile("cp.async.commit_group;");
    };

    const int q = lane >> 3, r = lane & 7;
    const int aRow = ((q & 1) << 3) + r;
    const int aCol = (q >> 1) << 4;
    const int bRow = ((q >> 1) << 3) + r;
    const int bCol = (q & 1) << 4;

    auto compute = [&]() {
        const uint32_t Ah = sb;
        const uint32_t Al = Ah + MTILE, Bh = Ah + 2 * MTILE, Bl = Ah + 3 * MTILE;
#pragma unroll
        for (int s = 0; s < 4; s++) {
            const int kOff = s * 32;
            uint32_t bh[4][2], bl[4][2];
#pragma unroll
            for (int np = 0; np < 2; np++) {
                uint32_t off = (uint32_t)(wn + np * 16 + bRow) * ROWB + kOff + bCol;
                ldsm4(bh[2 * np][0], bh[2 * np][1],
                      bh[2 * np + 1][0], bh[2 * np + 1][1], Bh + off);
                ldsm4(bl[2 * np][0], bl[2 * np][1],
                      bl[2 * np + 1][0], bl[2 * np + 1][1], Bl + off);
            }
#pragma unroll
            for (int mt = 0; mt < 4; mt++) {
                uint32_t ah[4], al[4];
                uint32_t off = (uint32_t)(wm + mt * 16 + aRow) * ROWB + kOff + aCol;
                ldsm4(ah[0], ah[1], ah[2], ah[3], Ah + off);
                ldsm4(al[0], al[1], al[2], al[3], Al + off);
#pragma unroll
                for (int nt = 0; nt < 4; nt++) {
                    mma16816(acc[mt][nt], ah, bh[nt]);
                    mma16816(acc[mt][nt], ah, bl[nt]);
                    mma16816(acc[mt][nt], al, bh[nt]);
                }
            }
        }
    };

    for (int c = 0; c < nch; c++) {
        issue(c);
        asm volatile("cp.async.wait_group 0;");
        __syncthreads();
        compute();
        __syncthreads();
    }

    const int gid = lane >> 2, tig = lane & 3;

    if (EPI == 3 && n0 >= 512) {
        // v tile: transpose through SMEM, then coalesced bf16 pair stores.
        float* st = (float*)smem;   // [n][m], stride 132
#pragma unroll
        for (int mt = 0; mt < 4; mt++)
#pragma unroll
            for (int half = 0; half < 2; half++) {
                const int m = wm + mt * 16 + gid + half * 8;
#pragma unroll
                for (int nt = 0; nt < 4; nt++) {
                    const int n = wn + nt * 8 + tig * 2;
                    st[n * 132 + m]       = acc[mt][nt][half * 2 + 0] + bias[n0 + n];
                    st[(n + 1) * 132 + m] = acc[mt][nt][half * 2 + 1] + bias[n0 + n + 1];
                }
            }
        __syncthreads();
        const long long bb2 = m0 >> 9;
        const int t0 = m0 & 511, nvb = n0 - 512;
#pragma unroll
        for (int it = 0; it < 32; it++) {
            int i = it * 256 + tid;
            int n = i >> 6, mc = (i & 63) << 1;
            float v0 = st[n * 132 + mc], v1 = st[n * 132 + mc + 1];
            __nv_bfloat16 h0 = __float2bfloat16(v0), h1 = __float2bfloat16(v1);
            long long gi = (bb2 * 768 + nvb + n) * 512 + t0 + mc;
            *(uint32_t*)&Dh[gi] = bpack(h0, h1);
            *(uint32_t*)&Dl[gi] =
                fpack(v0 - __bfloat162float(h0), v1 - __bfloat162float(h1));
        }
    } else {
#pragma unroll
        for (int mt = 0; mt < 4; mt++)
#pragma unroll
            for (int half = 0; half < 2; half++) {
                const long long m = m0 + wm + mt * 16 + gid + half * 8;
#pragma unroll
                for (int nt = 0; nt < 4; nt++) {
                    float v0 = acc[mt][nt][half * 2 + 0];
                    float v1 = acc[mt][nt][half * 2 + 1];
                    const int n = n0 + wn + nt * 8 + tig * 2;
                    if (EPI == 0) {
                        v0 *= alpha; v1 *= alpha;
                        if (bias) { v0 += bias[n]; v1 += bias[n + 1]; }
                        *(float2*)&Cf[m * ldc + n] = make_float2(v0, v1);
                    } else {  // EPI == 3, qk half
                        v0 += bias[n]; v1 += bias[n + 1];
                        __nv_bfloat16 h0 = __float2bfloat16(v0), h1 = __float2bfloat16(v1);
                        *(uint32_t*)&Ch[m * 512 + n] = bpack(h0, h1);
                        *(uint32_t*)&Cl[m * 512 + n] =
                            fpack(v0 - __bfloat162float(h0), v1 - __bfloat162float(h1));
                    }
                }
            }
    }
}

// ---------------- split-K finish: qe = sum(12 slabs) + bq; fp32 + pairs ------
__global__ void qe_finish()
{
    int idx = blockIdx.x * 256 + threadIdx.x;   // 32768 float4s
    int n4 = (idx % (NE / 4)) * 4;
    float4 s = ((const float4*)g_qeP)[idx];
#pragma unroll
    for (int k = 1; k < 12; k++) {
        float4 p = ((const float4*)g_qeP)[k * (512 * NE / 4) + idx];
        s.x += p.x; s.y += p.y; s.z += p.z; s.w += p.w;
    }
    s.x += g_bias[n4]; s.y += g_bias[n4 + 1];
    s.z += g_bias[n4 + 2]; s.w += g_bias[n4 + 3];
    ((float4*)g_qe)[idx] = s;
    uint2 hv, lv; split4(s, hv, lv);
    ((uint2*)g_qeh)[idx] = hv;
    ((uint2*)g_qel)[idx] = lv;
}

// ---------------- split-K finish: z = sum(4 slabs) ---------------------------
__global__ void z_finish()
{
    int idx = blockIdx.x * 256 + threadIdx.x;   // 98304 float4s
    float4 a = ((const float4*)g_zP)[idx];
#pragma unroll
    for (int k = 1; k < 4; k++) {
        float4 b = ((const float4*)g_zP)[k * (512 * H / 4) + idx];
        a.x += b.x; a.y += b.y; a.z += b.z; a.w += b.w;
    }
    ((float4*)g_z)[idx] = a;
}

// ---------------- weights: stacked WT pairs + WkN pairs + bias ---------------
__global__ void tsplit_all(const float* __restrict__ Wq, const float* __restrict__ Wk,
                           const float* __restrict__ Wv, const float* __restrict__ bq,
                           const float* __restrict__ bk, const float* __restrict__ bv)
{
    int idx = blockIdx.x * 256 + threadIdx.x;
    if (idx < 1280 * H) {
        const float* W; int Nn, nbase, local;
        if (idx < NE * H)            { W = Wq; Nn = NE; nbase = 0;   local = idx; }
        else if (idx < 2 * NE * H)   { W = Wk; Nn = NE; nbase = 256; local = idx - NE * H; }
        else                         { W = Wv; Nn = H;  nbase = 512; local = idx - 2 * NE * H; }
        int k = local / Nn, n = local - k * Nn;
        float x = W[local];                       // coalesced read
        __nv_bfloat16 h = __float2bfloat16(x);
        int oi = (nbase + n) * H + k;             // transposed scatter store
        g_Wh[oi] = h;
        g_Wl[oi] = __float2bfloat16(x - __bfloat162float(h));
    } else if (idx < 1280 * H + H * NE) {
        int local = idx - 1280 * H;
        float x = Wk[local];
        __nv_bfloat16 h = __float2bfloat16(x);
        g_WkNh[local] = h;
        g_WkNl[local] = __float2bfloat16(x - __bfloat162float(h));
    } else if (idx < 1280 * H + H * NE + 1280) {
        int j = idx - 1280 * H - H * NE;
        g_bias[j] = (j < 256) ? bq[j] : (j < 512) ? bk[j - 256] : bv[j - 512];
    }
}

// ---------------- gather + split region rows for qe GEMM ---------------------
__global__ void sgat_kernel(const float* __restrict__ xs)
{
    int idx = blockIdx.x * 256 + threadIdx.x;
    int m = idx / (H / 4), r4 = idx - m * (H / 4);
    int br = m >> 8, b = (m >> 3) & 31, l = m & 7;
    float4 v = ((const float4*)(xs + ((long long)b * S + (br ? 20 : 1) + l) * H))[r4];
    uint2 hv, lv; split4(v, hv, lv);
    ((uint2*)g_qAh)[idx] = hv;
    ((uint2*)g_qAl)[idx] = lv;
}

// ---------------- c[row] = qe[row]·bk ----------------------------------------
__global__ void c_kernel()
{
    int row = blockIdx.x * 8 + (threadIdx.x >> 5);
    int lane = threadIdx.x & 31;
    float p = 0.f;
#pragma unroll
    for (int i = 0; i < 8; i++) {
        int e = lane + i * 32;
        p += g_qe[row * NE + e] * g_bias[256 + e];
    }
#pragma unroll
    for (int o = 16; o > 0; o >>= 1) p += __shfl_xor_sync(0xffffffffu, p, o);
    if (lane == 0) g_c[row] = p;
}

// ---------------- u = Wa @ Wattn halves; cbase -------------------------------
__global__ void u_kernel(const float* __restrict__ Wa, const float* __restrict__ Wattn,
                         const float* __restrict__ ba, const float* __restrict__ battn)
{
    if (blockIdx.x < 48) {
        int gt = blockIdx.x * 256 + threadIdx.x;
        int g = gt >> 3, sub = gt & 7;
        int j = g / H, h = g - j * H;
        float acc = 0.f;
#pragma unroll 4
        for (int a = sub; a < AE; a += 8) acc += Wa[h * AE + a] * Wattn[j * AE + a];
        acc += __shfl_down_sync(0xffffffffu, acc, 4, 8);
        acc += __shfl_down_sync(0xffffffffu, acc, 2, 8);
        acc += __shfl_down_sync(0xffffffffu, acc, 1, 8);
        if (sub == 0) g_u[g] = acc;
    } else {
        __shared__ float red[256];
        int tid = threadIdx.x;
        float v = 0.f;
        if (tid < AE) v = ba[tid] * (Wattn[tid] + Wattn[AE + tid]);
        red[tid] = v; __syncthreads();
        for (int s2 = 128; s2 > 0; s2 >>= 1) {
            if (tid < s2) red[tid] += red[tid + s2];
            __syncthreads();
        }
        if (tid == 0) g_u[2 * H] = red[0] + battn[0];
    }
}

// ---------------- per-(br,b,n): scores -> softmax -> message (+ fused md) ----
__global__ __launch_bounds__(256) void neigh_kernel(
    const float* __restrict__ e1, const float* __restrict__ e2)
{
    __shared__ float zs[RL * H];        // 24 KB
    __shared__ float es[T * 196];       // 24.5 KB
    __shared__ float awT[T * 8];        // [t][l]
    __shared__ float cs[RL];
    __shared__ float mdred[256];
    float* red = es;                    // 8 x 256 reduction buffer (aliases es)

    int br = blockIdx.x >> 10;
    int b = (blockIdx.x >> 5) & 31, n = blockIdx.x & 31;
    int tid = threadIdx.x;
    const float* emb = (br ? e2 : e1) + (long long)(b * NN + n) * T * H;
    const float4* eb4 = (const float4*)emb;

    const float4* z4 = (const float4*)(g_z + (long long)(br * 256 + b * 8) * H);
#pragma unroll
    for (int it = 0; it < 6; it++) {
        int i = it * 256 + tid;
        *(float4*)&zs[i * 4] = z4[i];
    }
    if (tid < 8) cs[tid] = g_c[br * 256 + b * 8 + tid];
    __syncthreads();

    const int tt = tid & 31, sh = tid >> 5;
    float acc8[8];
#pragma unroll
    for (int l = 0; l < 8; l++) acc8[l] = 0.f;

#pragma unroll
    for (int ch = 0; ch < 4; ch++) {
        for (int i = tid; i < T * 48; i += 256) {
            int t2 = i / 48, h4 = i - t2 * 48;
            *(float4*)&es[t2 * 196 + h4 * 4] = eb4[t2 * (H / 4) + ch * 48 + h4];
        }
        __syncthreads();
        const float4* er = (const float4*)&es[tt * 196 + sh * 24];
        float4 ev[6];
#pragma unroll
        for (int j = 0; j < 6; j++) ev[j] = er[j];
#pragma unroll
        for (int l = 0; l < 8; l++) {
            const float4* zr = (const float4*)&zs[l * H + ch * 192 + sh * 24];
            float a = 0.f;
#pragma unroll
            for (int j = 0; j < 6; j++) {
                float4 zv = zr[j];
                a += ev[j].x * zv.x + ev[j].y * zv.y + ev[j].z * zv.z + ev[j].w * zv.w;
            }
            acc8[l] += a;
        }
        __syncthreads();
    }

#pragma unroll
    for (int l = 0; l < 8; l++) red[sh * 256 + l * 32 + tt] = acc8[l];
    __syncthreads();

    const int l = tid >> 5;
    float s = 0.f;
#pragma unroll
    for (int k = 0; k < 8; k++) s += red[k * 256 + tid];
    s = (s + cs[l]) * SCALE;
    float m = s;
#pragma unroll
    for (int o = 16; o > 0; o >>= 1) m = fmaxf(m, __shfl_xor_sync(0xffffffffu, m, o));
    float ex = __expf(s - m), sum = ex;
#pragma unroll
    for (int o = 16; o > 0; o >>= 1) sum += __shfl_xor_sync(0xffffffffu, sum, o);
    awT[tt * 8 + l] = ex / sum;
    __syncthreads();

    // message phase + fused md partial (dot of all messages with u2)
    float mdp = 0.f;
    if (tid < H / 4) {
        const int h4 = tid;
        float4 mac[8];
#pragma unroll
        for (int l2 = 0; l2 < 8; l2++) mac[l2] = make_float4(0.f, 0.f, 0.f, 0.f);
        for (int t2 = 0; t2 < T; t2++) {
            float4 e = eb4[t2 * (H / 4) + h4];
            float4 w0 = *(const float4*)&awT[t2 * 8];
            float4 w1 = *(const float4*)&awT[t2 * 8 + 4];
            float wv[8] = {w0.x, w0.y, w0.z, w0.w, w1.x, w1.y, w1.z, w1.w};
#pragma unroll
            for (int l2 = 0; l2 < 8; l2++) {
                mac[l2].x += wv[l2] * e.x; mac[l2].y += wv[l2] * e.y;
                mac[l2].z += wv[l2] * e.z; mac[l2].w += wv[l2] * e.w;
            }
        }
        float4* mb4 = (float4*)((br ? g_msg2 : g_msg1) + (long long)(b * NN + n) * RL * H);
        const float4 u2 = *(const float4*)&g_u[H + h4 * 4];
#pragma unroll
        for (int l2 = 0; l2 < 8; l2++) {
            mb4[l2 * (H / 4) + h4] = mac[l2];
            mdp += mac[l2].x * u2.x + mac[l2].y * u2.y
                 + mac[l2].z * u2.z + mac[l2].w * u2.w;
        }
    }
    mdred[tid] = mdp;
    __syncthreads();
    for (int s2 = 128; s2 > 0; s2 >>= 1) {
        if (tid < s2) mdred[tid] += mdred[tid + s2];
        __syncthreads();
    }
    if (tid == 0) g_md[(br * Bn + b) * NN + n] = mdred[0] * (1.f / RL);
}

// ---------------- region gate: feas dot only (msg dots fused in neigh) -------
__global__ __launch_bounds__(128) void rscore_kernel(const float* __restrict__ xs)
{
    __shared__ float wred[4];
    int br = blockIdx.x >> 5, b = blockIdx.x & 31;
    int tid = threadIdx.x;
    const float* src = xs + ((long long)b * S + (br ? 20 : 1)) * H;
    const float4* s4 = (const float4*)src;
    float p = 0.f;
#pragma unroll
    for (int it = 0; it < RL * H / 4 / 128; it++) {
        int i = it * 128 + tid;
        float4 v = s4[i];
        const float* up = g_u + (i % (H / 4)) * 4;
        p += v.x * up[0] + v.y * up[1] + v.z * up[2] + v.w * up[3];
    }
#pragma unroll
    for (int o = 16; o > 0; o >>= 1) p += __shfl_xor_sync(0xffffffffu, p, o);
    if ((tid & 31) == 0) wred[tid >> 5] = p;
    __syncthreads();
    if (tid == 0)
        g_feas[br * Bn + b] = (wred[0] + wred[1] + wred[2] + wred[3]) * (1.f / RL);
}

__global__ void rsoftmax_kernel(const float* __restrict__ dist1,
                                const float* __restrict__ dist2,
                                const float* __restrict__ wb,
                                const float* __restrict__ bb)
{
    int br = blockIdx.x >> 5, b = blockIdx.x & 31;
    int lane = threadIdx.x;
    float pre = g_feas[br * Bn + b] + g_md[(br * Bn + b) * NN + lane] + g_u[2 * H];
    float z = pre >= 0.f ? pre : NEG * pre;
    const float* dist = br ? dist2 : dist1;
    float v = z + dist[b * NN + lane] * wb[0] + bb[0];
    float m = v;
#pragma unroll
    for (int o = 16; o > 0; o >>= 1) m = fmaxf(m, __shfl_xor_sync(0xffffffffu, m, o));
    float e = __expf(v - m), s = e;
#pragma unroll
    for (int o = 16; o > 0; o >>= 1) s += __shfl_xor_sync(0xffffffffu, s, o);
    (br ? g_att2 : g_att1)[b * NN + lane] = e / s;
}

// ---------------- x = xs (+ gated messages) -> bf16 pairs --------------------
__global__ void build_x_kernel(const float* __restrict__ xs)
{
    int idx = blockIdx.x * 256 + threadIdx.x;
    float4 v = ((const float4*)xs)[idx];
    int h4 = idx % (H / 4);
    int s = (idx / (H / 4)) % S;
    int b = idx / (S * H / 4);
    if (s >= 1 && s < 9) {
        int l = s - 1;
        const float4* m4 = (const float4*)g_msg1;
#pragma unroll 4
        for (int n = 0; n < NN; n++) {
            float a = g_att1[b * NN + n];
            float4 m = m4[((b * NN + n) * RL + l) * (H / 4) + h4];
            v.x += a * m.x; v.y += a * m.y; v.z += a * m.z; v.w += a * m.w;
        }
    } else if (s >= 20 && s < 28) {
        int l = s - 20;
        const float4* m4 = (const float4*)g_msg2;
#pragma unroll 4
        for (int n = 0; n < NN; n++) {
            float a = g_att2[b * NN + n];
            float4 m = m4[((b * NN + n) * RL + l) * (H / 4) + h4];
            v.x += a * m.x; v.y += a * m.y; v.z += a * m.z; v.w += a * m.w;
        }
    }
    uint2 hv, lv; split4(v, hv, lv);
    ((uint2*)g_xh)[idx] = hv;
    ((uint2*)g_xl)[idx] = lv;
}

// ---------------- row softmax (warp/row) -> bf16 pairs -----------------------
__global__ __launch_bounds__(256) void softmax_rows_kernel()
{
    int warp = threadIdx.x >> 5, lane = threadIdx.x & 31;
    long long row = (long long)blockIdx.x * 8 + warp;
    const float4* r4 = (const float4*)(g_probs + row * S);
    float4 x[4];
    float m = -3.4e38f;
#pragma unroll
    for (int k = 0; k < 4; k++) {
        x[k] = r4[lane + 32 * k];
        m = fmaxf(m, fmaxf(fmaxf(x[k].x, x[k].y), fmaxf(x[k].z, x[k].w)));
    }
#pragma unroll
    for (int o = 16; o > 0; o >>= 1) m = fmaxf(m, __shfl_xor_sync(0xffffffffu, m, o));
    float s = 0.f;
#pragma unroll
    for (int k = 0; k < 4; k++) {
        x[k].x = __expf(x[k].x - m); x[k].y = __expf(x[k].y - m);
        x[k].z = __expf(x[k].z - m); x[k].w = __expf(x[k].w - m);
        s += x[k].x + x[k].y + x[k].z + x[k].w;
    }
#pragma unroll
    for (int o = 16; o > 0; o >>= 1) s += __shfl_xor_sync(0xffffffffu, s, o);
    float inv = 1.f / s;
    uint2* ph4 = (uint2*)(g_ph + row * S);
    uint2* pl4 = (uint2*)(g_pl + row * S);
#pragma unroll
    for (int k = 0; k < 4; k++) {
        x[k].x *= inv; x[k].y *= inv; x[k].z *= inv; x[k].w *= inv;
        uint2 hv, lv; split4(x[k], hv, lv);
        ph4[lane + 32 * k] = hv;
        pl4[lane + 32 * k] = lv;
    }
}

// ---------------- launch ----------------
extern "C" void kernel_launch(void* const* d_in, const int* in_sizes, int n_in,
                              void* d_out, int out_size)
{
    const float* xs    = (const float*)d_in[0];
    const float* n1emb = (const float*)d_in[1];
    const float* n2emb = (const float*)d_in[2];
    const float* dist1 = (const float*)d_in[3];
    const float* dist2 = (const float*)d_in[4];
    const float* Wq    = (const float*)d_in[5];
    const float* bq    = (const float*)d_in[6];
    const float* Wk    = (const float*)d_in[7];
    const float* bk    = (const float*)d_in[8];
    const float* Wv    = (const float*)d_in[9];
    const float* bv    = (const float*)d_in[10];
    const float* Wa    = (const float*)d_in[11];
    const float* ba    = (const float*)d_in[12];
    const float* Wattn = (const float*)d_in[13];
    const float* battn = (const float*)d_in[14];
    const float* wb    = (const float*)d_in[15];
    const float* bb    = (const float*)d_in[16];
    float* out = (float*)d_out;

    float *pp, *pqeP, *pzP, *pbias;
    __nv_bfloat16 *pwh, *pwl, *pwknh, *pwknl, *pqeh, *pqel, *pxh, *pxl,
                  *pqkh, *pqkl, *pvh, *pvl, *pph, *ppl, *pah, *pal;
    cudaGetSymbolAddress((void**)&pp,    g_probs);
    cudaGetSymbolAddress((void**)&pqeP,  g_qeP);
    cudaGetSymbolAddress((void**)&pzP,   g_zP);
    cudaGetSymbolAddress((void**)&pbias, g_bias);
    cudaGetSymbolAddress((void**)&pwh,   g_Wh);
    cudaGetSymbolAddress((void**)&pwl,   g_Wl);
    cudaGetSymbolAddress((void**)&pwknh, g_WkNh);
    cudaGetSymbolAddress((void**)&pwknl, g_WkNl);
    cudaGetSymbolAddress((void**)&pqeh,  g_qeh);
    cudaGetSymbolAddress((void**)&pqel,  g_qel);
    cudaGetSymbolAddress((void**)&pxh,   g_xh);
    cudaGetSymbolAddress((void**)&pxl,   g_xl);
    cudaGetSymbolAddress((void**)&pqkh,  g_qkh);
    cudaGetSymbolAddress((void**)&pqkl,  g_qkl);
    cudaGetSymbolAddress((void**)&pvh,   g_vTh);
    cudaGetSymbolAddress((void**)&pvl,   g_vTl);
    cudaGetSymbolAddress((void**)&pph,   g_ph);
    cudaGetSymbolAddress((void**)&ppl,   g_pl);
    cudaGetSymbolAddress((void**)&pah,   g_qAh);
    cudaGetSymbolAddress((void**)&pal,   g_qAl);

    cudaFuncSetAttribute(bgemm<0, false>, cudaFuncAttributeMaxDynamicSharedMemorySize, BG_SMEM);
    cudaFuncSetAttribute(bgemm<0, true>,  cudaFuncAttributeMaxDynamicSharedMemorySize, BG_SMEM);
    cudaFuncSetAttribute(bgemm<3, false>, cudaFuncAttributeMaxDynamicSharedMemorySize, BG_SMEM);

    // prep
    tsplit_all<<<(1280 * H + H * NE + 1280 + 255) / 256, 256>>>(Wq, Wk, Wv, bq, bk, bv);
    u_kernel<<<49, 256>>>(Wa, Wattn, ba, battn);
    sgat_kernel<<<512 * (H / 4) / 256, 256>>>(xs);

    // qe slabs: split-K 12 x 64 over K=768  (grid 2x4x12 = 96 CTAs, 1 chunk each)
    bgemm<0, true><<<dim3(2, 4, 12), 256, BG_SMEM>>>(
        pah, pal, pwh, pwl, nullptr, pqeP, nullptr, nullptr, nullptr, nullptr,
        H, H, NE, 64, 1.f, 0, 0, (long long)512 * NE);
    qe_finish<<<128, 256>>>();

    // z slabs: split-K 4 x 64 over K=256 (grid 6x4x4 = 96 CTAs, 1 chunk each)
    bgemm<0, true><<<dim3(6, 4, 4), 256, BG_SMEM>>>(
        pqeh, pqel, pwknh, pwknl, nullptr, pzP, nullptr, nullptr, nullptr, nullptr,
        NE, NE, H, 64, 1.f, 0, 0, (long long)512 * H);
    z_finish<<<384, 256>>>();
    c_kernel<<<64, 256>>>();

    // neighbor attention via emb·z + messages + fused md (both branches)
    neigh_kernel<<<2 * Bn * NN, 256>>>(n1emb, n2emb);

    // gate attention + x pairs
    rscore_kernel<<<2 * Bn, 128>>>(xs);
    rsoftmax_kernel<<<2 * Bn, 32>>>(dist1, dist2, wb, bb);
    build_x_kernel<<<(Bn * S * H / 4) / 256, 256>>>(xs);

    // fused q/k/v projections: M = 16384 -> 128 M-tiles, N = 1280 -> 10 N-tiles
    bgemm<3, false><<<dim3(10, 128, 1), 256, BG_SMEM>>>(
        pxh, pxl, pwh, pwl, pbias, nullptr, pqkh, pqkl, pvh, pvl,
        H, H, 512, H, 1.f, 0, 0, 0);

    // scores = SCALE * q @ k^T (batched, grid 4x4x32 = 512)
    bgemm<0, false><<<dim3(4, 4, 32), 256, BG_SMEM>>>(
        pqkh, pqkl, pqkh + 256, pqkl + 256, nullptr, pp,
        nullptr, nullptr, nullptr, nullptr,
        512, 512, S, NE, SCALE,
        (long long)S * 512, (long long)S * 512, (long long)S * S);

    softmax_rows_kernel<<<Bn * S / 8, 256>>>();

    // out = probs @ v (batched, grid 6x4x32 = 768)
    bgemm<0, false><<<dim3(6, 4, 32), 256, BG_SMEM>>>(
        pph, ppl, pvh, pvl, nullptr, out, nullptr, nullptr, nullptr, nullptr,
        512, 512, H, S, 1.f,
        (long long)S * S, (long long)H * S, (long long)S * H);
}